// round 1
// baseline (speedup 1.0000x reference)
#include <cuda_runtime.h>
#include <math.h>

#define B_ 8
#define H_ 512
#define L_ 4096
#define N_ 32
#define HN (H_ * N_)

// Scratch: gelu(y) intermediate, and precomputed recurrence params.
__device__ float d_g[(size_t)B_ * H_ * L_];
__device__ float d_wr[HN], d_wi[HN], d_csr[HN], d_csi[HN];

// ---------------------------------------------------------------------------
// Kernel 1: per (h,n) precompute  w = exp(dt*A),  2*Cs = 2*C*(w-1)/A
// ---------------------------------------------------------------------------
__global__ void prep_kernel(const float* __restrict__ log_dt,
                            const float* __restrict__ log_A_real,
                            const float* __restrict__ A_imag,
                            const float* __restrict__ C)
{
    int idx = blockIdx.x * blockDim.x + threadIdx.x;
    if (idx >= HN) return;
    int h = idx / N_;
    float dt = expf(log_dt[h]);
    float ar = -expf(log_A_real[idx]);   // real(A)  (negative)
    float ai = A_imag[idx];              // imag(A)
    // w = exp(dt*(ar + i*ai))
    float mag = expf(dt * ar);
    float wr = mag * cosf(dt * ai);
    float wi = mag * sinf(dt * ai);
    // q = (w - 1) / A
    float den = ar * ar + ai * ai;
    float nr = wr - 1.0f, ni = wi;
    float qr = (nr * ar + ni * ai) / den;
    float qi = (ni * ar - nr * ai) / den;
    // Cs = (Cr + i*Ci) * q ; fold the factor 2 from 2*Re(...)
    float Cr = C[2 * idx], Ci = C[2 * idx + 1];
    d_wr[idx]  = wr;
    d_wi[idx]  = wi;
    d_csr[idx] = 2.0f * (Cr * qr - Ci * qi);
    d_csi[idx] = 2.0f * (Cr * qi + Ci * qr);
}

// ---------------------------------------------------------------------------
// Kernel 2: sequential scan, one warp per (b,h). Lane n holds complex state
// x_n; per step: x = w*x + u, y = sum_n Re(Cs_n * x_n) (butterfly reduce),
// y += D*u, then GELU (exact erf) applied once per 32-step group, and a
// coalesced 128B store of the group's outputs.
// ---------------------------------------------------------------------------
__global__ __launch_bounds__(128) void scan_kernel(const float* __restrict__ u,
                                                   const float* __restrict__ D)
{
    int warp = (blockIdx.x * blockDim.x + threadIdx.x) >> 5;
    int lane = threadIdx.x & 31;
    int b = warp / H_;
    int h = warp - b * H_;
    int idx = h * N_ + lane;

    float wr = d_wr[idx], wi = d_wi[idx];
    float cr = d_csr[idx], ci = d_csi[idx];
    float nci = -ci;
    float Dh = D[h];

    const float* up = u   + ((size_t)b * H_ + h) * L_;
    float*       gp = d_g + ((size_t)b * H_ + h) * L_;

    float xr = 0.0f, xi = 0.0f;

    for (int l0 = 0; l0 < L_; l0 += 32) {
        float uv = up[l0 + lane];          // coalesced preload of 32 u's
        float keep = 0.0f;
        #pragma unroll
        for (int t = 0; t < 32; t++) {
            float ut = __shfl_sync(0xffffffffu, uv, t);
            // x = w*x + u
            float t0  = fmaf(-wi, xi, ut);
            float t1  = wi * xr;
            float nxr = fmaf(wr, xr, t0);
            float nxi = fmaf(wr, xi, t1);
            xr = nxr; xi = nxi;
            // contribution Re(Cs * x)   (factor 2 folded into Cs)
            float c = fmaf(cr, xr, nci * xi);
            // warp sum over the 32 modes
            c += __shfl_xor_sync(0xffffffffu, c, 16);
            c += __shfl_xor_sync(0xffffffffu, c, 8);
            c += __shfl_xor_sync(0xffffffffu, c, 4);
            c += __shfl_xor_sync(0xffffffffu, c, 2);
            c += __shfl_xor_sync(0xffffffffu, c, 1);
            float y = fmaf(Dh, ut, c);     // D skip
            if (t == lane) keep = y;       // lane t owns timestep l0+t
        }
        // exact-erf GELU, once per group per lane
        float gv = 0.5f * keep * (1.0f + erff(keep * 0.70710678118654752f));
        gp[l0 + lane] = gv;                // coalesced store
    }
}

// ---------------------------------------------------------------------------
// Kernel 3: fused 1x1-conv (GEMM) + GLU.
//   pre[o,l] = sum_k W[o,k]*g[b,k,l] + bias[o],  o in [0,2H)
//   out[b,h,l] = pre[h,l] * sigmoid(pre[h+H,l])
// Tile: 64 (h-out) x 64 (l), BK=16, 256 threads, 4x4 (x2 for gate) per thread.
// ---------------------------------------------------------------------------
#define BM 64
#define BN 64
#define BK 16

__global__ __launch_bounds__(256) void gemm_glu_kernel(const float* __restrict__ W,
                                                       const float* __restrict__ bias,
                                                       float* __restrict__ out)
{
    int b  = blockIdx.z;
    int h0 = blockIdx.y * BM;
    int l0 = blockIdx.x * BN;

    __shared__ float Wa[BK][BM];
    __shared__ float Wb[BK][BM];
    __shared__ float Gs[BK][BN];

    int t  = threadIdx.x;
    int ty = t >> 4;        // 0..15
    int tx = t & 15;        // 0..15

    // load indices
    int lo = t >> 2;          // 0..63  : row within W tile
    int lk = (t & 3) * 4;     // 0,4,8,12 : k offset (float4)

    const float* gbase = d_g + (size_t)b * H_ * L_;

    float acc_a[4][4];
    float acc_b[4][4];
    #pragma unroll
    for (int i = 0; i < 4; i++)
        #pragma unroll
        for (int j = 0; j < 4; j++) { acc_a[i][j] = 0.0f; acc_b[i][j] = 0.0f; }

    for (int k0 = 0; k0 < H_; k0 += BK) {
        float4 wa4 = *(const float4*)&W[(size_t)(h0 + lo) * H_ + k0 + lk];
        float4 wb4 = *(const float4*)&W[(size_t)(h0 + H_ + lo) * H_ + k0 + lk];
        float4 g4  = *(const float4*)&gbase[(size_t)(k0 + ty) * L_ + l0 + tx * 4];

        __syncthreads();
        Wa[lk + 0][lo] = wa4.x; Wa[lk + 1][lo] = wa4.y;
        Wa[lk + 2][lo] = wa4.z; Wa[lk + 3][lo] = wa4.w;
        Wb[lk + 0][lo] = wb4.x; Wb[lk + 1][lo] = wb4.y;
        Wb[lk + 2][lo] = wb4.z; Wb[lk + 3][lo] = wb4.w;
        *(float4*)&Gs[ty][tx * 4] = g4;
        __syncthreads();

        #pragma unroll
        for (int k = 0; k < BK; k++) {
            float4 av = *(const float4*)&Wa[k][ty * 4];
            float4 bv = *(const float4*)&Wb[k][ty * 4];
            float4 gv = *(const float4*)&Gs[k][tx * 4];
            float a[4] = {av.x, av.y, av.z, av.w};
            float bb[4] = {bv.x, bv.y, bv.z, bv.w};
            float g[4] = {gv.x, gv.y, gv.z, gv.w};
            #pragma unroll
            for (int i = 0; i < 4; i++)
                #pragma unroll
                for (int j = 0; j < 4; j++) {
                    acc_a[i][j] = fmaf(a[i],  g[j], acc_a[i][j]);
                    acc_b[i][j] = fmaf(bb[i], g[j], acc_b[i][j]);
                }
        }
    }

    #pragma unroll
    for (int i = 0; i < 4; i++) {
        int h = h0 + ty * 4 + i;
        float ba = bias[h];
        float bg = bias[h + H_];
        float4 o4;
        float res[4];
        #pragma unroll
        for (int j = 0; j < 4; j++) {
            float a    = acc_a[i][j] + ba;
            float gate = acc_b[i][j] + bg;
            res[j] = a * (1.0f / (1.0f + expf(-gate)));
        }
        o4.x = res[0]; o4.y = res[1]; o4.z = res[2]; o4.w = res[3];
        *(float4*)&out[((size_t)b * H_ + h) * L_ + l0 + tx * 4] = o4;
    }
}

// ---------------------------------------------------------------------------
extern "C" void kernel_launch(void* const* d_in, const int* in_sizes, int n_in,
                              void* d_out, int out_size)
{
    const float* u          = (const float*)d_in[0];
    const float* log_dt     = (const float*)d_in[1];
    const float* log_A_real = (const float*)d_in[2];
    const float* A_imag     = (const float*)d_in[3];
    const float* C          = (const float*)d_in[4];
    const float* D          = (const float*)d_in[5];
    const float* W_out      = (const float*)d_in[6];
    const float* b_out      = (const float*)d_in[7];
    float* out = (float*)d_out;

    prep_kernel<<<(HN + 127) / 128, 128>>>(log_dt, log_A_real, A_imag, C);

    // one warp per (b,h): B*H = 4096 warps, 4 warps per block
    scan_kernel<<<(B_ * H_) / 4, 128>>>(u, D);

    dim3 grid(L_ / BN, H_ / BM, B_);
    gemm_glu_kernel<<<grid, 256>>>(W_out, b_out, out);
}

// round 3
// speedup vs baseline: 1.1360x; 1.1360x over previous
#include <cuda_runtime.h>
#include <cuda_bf16.h>
#include <math.h>
#include <stdint.h>

#define B_ 8
#define H_ 512
#define L_ 4096
#define N_ 32
#define HN (H_ * N_)
#define O_ (2 * H_)

// ---------------- scratch (__device__ globals) -----------------------------
__device__ float d_wr[HN], d_wi[HN], d_csr[HN], d_csi[HN];
// transposed gelu(scan) output, bf16 hi/lo: gT[b][l][h]
__device__ __nv_bfloat16 d_gTh[(size_t)B_ * L_ * H_];
__device__ __nv_bfloat16 d_gTl[(size_t)B_ * L_ * H_];
// W split bf16 hi/lo: [1024][512]
__device__ __nv_bfloat16 d_Wh[(size_t)O_ * H_];
__device__ __nv_bfloat16 d_Wl[(size_t)O_ * H_];

// ---------------------------------------------------------------------------
__device__ __forceinline__ uint32_t smem_u32(const void* p) {
    uint32_t a;
    asm("{ .reg .u64 t; cvta.to.shared.u64 t, %1; cvt.u32.u64 %0, t; }"
        : "=r"(a) : "l"(p));
    return a;
}

#define CP_ASYNC16(dst, src) \
    asm volatile("cp.async.cg.shared.global [%0], [%1], 16;" :: "r"(dst), "l"(src))
#define CP_COMMIT() asm volatile("cp.async.commit_group;" ::: "memory")
#define CP_WAIT1()  asm volatile("cp.async.wait_group 1;" ::: "memory")
#define CP_WAIT0()  asm volatile("cp.async.wait_group 0;" ::: "memory")

__device__ __forceinline__ void ldsm4(uint32_t* r, uint32_t addr) {
    asm volatile("ldmatrix.sync.aligned.m8n8.x4.shared.b16 {%0,%1,%2,%3}, [%4];"
                 : "=r"(r[0]), "=r"(r[1]), "=r"(r[2]), "=r"(r[3]) : "r"(addr));
}

__device__ __forceinline__ void mma16816(float* d, const uint32_t* a,
                                         uint32_t b0, uint32_t b1) {
    asm volatile("mma.sync.aligned.m16n8k16.row.col.f32.bf16.bf16.f32 "
                 "{%0,%1,%2,%3}, {%4,%5,%6,%7}, {%8,%9}, {%0,%1,%2,%3};"
                 : "+f"(d[0]), "+f"(d[1]), "+f"(d[2]), "+f"(d[3])
                 : "r"(a[0]), "r"(a[1]), "r"(a[2]), "r"(a[3]), "r"(b0), "r"(b1));
}

// ---------------------------------------------------------------------------
// Kernel 1: per (h,n) precompute  w = exp(dt*A),  2*Cs = 2*C*(w-1)/A
// ---------------------------------------------------------------------------
__global__ void prep_kernel(const float* __restrict__ log_dt,
                            const float* __restrict__ log_A_real,
                            const float* __restrict__ A_imag,
                            const float* __restrict__ C)
{
    int idx = blockIdx.x * blockDim.x + threadIdx.x;
    if (idx >= HN) return;
    int h = idx / N_;
    float dt = expf(log_dt[h]);
    float ar = -expf(log_A_real[idx]);
    float ai = A_imag[idx];
    float mag = expf(dt * ar);
    float wr = mag * cosf(dt * ai);
    float wi = mag * sinf(dt * ai);
    float den = ar * ar + ai * ai;
    float nr = wr - 1.0f, ni = wi;
    float qr = (nr * ar + ni * ai) / den;
    float qi = (ni * ar - nr * ai) / den;
    float Cr = C[2 * idx], Ci = C[2 * idx + 1];
    d_wr[idx]  = wr;
    d_wi[idx]  = wi;
    d_csr[idx] = 2.0f * (Cr * qr - Ci * qi);
    d_csi[idx] = 2.0f * (Cr * qi + Ci * qr);
}

// ---------------------------------------------------------------------------
// Kernel 1b: split W into bf16 hi/lo
// ---------------------------------------------------------------------------
__global__ void wsplit_kernel(const float* __restrict__ W)
{
    int idx = blockIdx.x * blockDim.x + threadIdx.x;
    if (idx >= O_ * H_) return;
    float w = W[idx];
    __nv_bfloat16 hi = __float2bfloat16(w);
    __nv_bfloat16 lo = __float2bfloat16(w - __bfloat162float(hi));
    d_Wh[idx] = hi;
    d_Wl[idx] = lo;
}

// ---------------------------------------------------------------------------
// Kernel 2: sequential scan, one warp per (b,h); writes transposed bf16 hi/lo
// ---------------------------------------------------------------------------
__global__ __launch_bounds__(128) void scan_kernel(const float* __restrict__ u,
                                                   const float* __restrict__ D)
{
    int warp = (blockIdx.x * blockDim.x + threadIdx.x) >> 5;
    int lane = threadIdx.x & 31;
    int b = warp / H_;
    int h = warp - b * H_;
    int idx = h * N_ + lane;

    float wr = d_wr[idx], wi = d_wi[idx];
    float cr = d_csr[idx], ci = d_csi[idx];
    float nci = -ci;
    float Dh = D[h];

    const float* up = u + ((size_t)b * H_ + h) * L_;
    size_t tbase = (size_t)b * L_ * H_ + h;

    float xr = 0.0f, xi = 0.0f;

    for (int l0 = 0; l0 < L_; l0 += 32) {
        float uv = up[l0 + lane];
        float keep = 0.0f;
        #pragma unroll
        for (int t = 0; t < 32; t++) {
            float ut = __shfl_sync(0xffffffffu, uv, t);
            float t0  = fmaf(-wi, xi, ut);
            float t1  = wi * xr;
            float nxr = fmaf(wr, xr, t0);
            float nxi = fmaf(wr, xi, t1);
            xr = nxr; xi = nxi;
            float c = fmaf(cr, xr, nci * xi);
            c += __shfl_xor_sync(0xffffffffu, c, 16);
            c += __shfl_xor_sync(0xffffffffu, c, 8);
            c += __shfl_xor_sync(0xffffffffu, c, 4);
            c += __shfl_xor_sync(0xffffffffu, c, 2);
            c += __shfl_xor_sync(0xffffffffu, c, 1);
            float y = fmaf(Dh, ut, c);
            if (t == lane) keep = y;
        }
        float gv = 0.5f * keep * (1.0f + erff(keep * 0.70710678118654752f));
        __nv_bfloat16 hi = __float2bfloat16(gv);
        __nv_bfloat16 lo = __float2bfloat16(gv - __bfloat162float(hi));
        size_t o = tbase + (size_t)(l0 + lane) * H_;
        d_gTh[o] = hi;
        d_gTl[o] = lo;
    }
}

// ---------------------------------------------------------------------------
// Kernel 3: mma.sync bf16 split GEMM + GLU.
//   pre[o,l] = sum_k W[o,k] g[k,l] + bias[o];  out[b,h,l] = pre[h]*sig(pre[h+512])
// CTA: M=128 (rows 0-63: a channels h0..h0+63, rows 64-127: gate channels
// 512+h0..+63), N=128 l-cols, K chunks of 16, double-buffered cp.async.
// 8 warps (4M x 2N), warp tile 32x64. Split bf16: hi*hi + hi*lo + lo*hi.
// ---------------------------------------------------------------------------
#define BK 16
#define SSTR 48                    // smem row stride in BYTES (16 bf16 + 8 pad)
#define TILEB (128 * SSTR)         // 6144 bytes per tile
#define STAGEB (4 * TILEB)         // Ah, Al, Bh, Bl = 24576
#define SMEM_BYTES (2 * STAGEB)    // 49152 (fits default limit)
#define NSTAGE (H_ / BK)           // 32

__global__ __launch_bounds__(256, 1) void gemm_glu_mma(const float* __restrict__ bias,
                                                       float* __restrict__ out)
{
    extern __shared__ char smem[];
    const int tid  = threadIdx.x;
    const int wid  = tid >> 5;
    const int lane = tid & 31;

    const int nblk = blockIdx.x;            // 0..255
    const int b    = nblk >> 5;
    const int l0   = (nblk & 31) * 128;
    const int h0   = blockIdx.y * 64;

    const uint32_t sb = smem_u32(smem);

    // ---- per-thread cp.async mapping: 4 x 16B per stage ----
    // stage tile = 4 tiles x 128 rows x 2 segs(16B) = 1024 txns / 256 thr
    const char* srcs[4];
    uint32_t    dsts[4];
    #pragma unroll
    for (int j = 0; j < 4; j++) {
        int id   = tid + 256 * j;
        int tile = id >> 8;
        int rem  = id & 255;
        int r    = rem >> 1;
        int seg  = rem & 1;
        const __nv_bfloat16* base;
        size_t rowoff;
        if (tile < 2) {
            int arow = h0 + r + ((r >= 64) ? 448 : 0);   // gate half at +512
            base = (tile == 0) ? d_Wh : d_Wl;
            rowoff = (size_t)arow * H_;
        } else {
            base = ((tile == 2) ? d_gTh : d_gTl) + (size_t)b * L_ * H_;
            rowoff = (size_t)(l0 + r) * H_;
        }
        srcs[j] = (const char*)(base + rowoff) + seg * 16;
        dsts[j] = sb + tile * TILEB + r * SSTR + seg * 16;
    }

    // issue stage 0
    #pragma unroll
    for (int j = 0; j < 4; j++) CP_ASYNC16(dsts[j], srcs[j]);
    CP_COMMIT();

    float acc[2][8][4];
    #pragma unroll
    for (int mf = 0; mf < 2; mf++)
        #pragma unroll
        for (int nf = 0; nf < 8; nf++)
            #pragma unroll
            for (int e = 0; e < 4; e++) acc[mf][nf][e] = 0.0f;

    const int wm = wid >> 1;      // 0..3 (M)
    const int wn = wid & 1;       // 0..1 (N)

    for (int s = 0; s < NSTAGE; s++) {
        if (s + 1 < NSTAGE) {
            uint32_t dbo = ((s + 1) & 1) * STAGEB;
            size_t   sbo = (size_t)(s + 1) * (BK * 2);   // 32 bytes per stage
            #pragma unroll
            for (int j = 0; j < 4; j++) CP_ASYNC16(dsts[j] + dbo, srcs[j] + sbo);
            CP_COMMIT();
            CP_WAIT1();
        } else {
            CP_WAIT0();
        }
        __syncthreads();

        const uint32_t st = sb + (s & 1) * STAGEB;

        // A fragments (rows wm*32 .. +32): 2 m16 frags, hi & lo
        uint32_t aH[2][4], aL[2][4];
        {
            int rr0 = wm * 32 + (lane & 15);
            int kk  = (lane >> 4) << 3;       // 0 or 8
            #pragma unroll
            for (int mf = 0; mf < 2; mf++) {
                uint32_t addr = st + (rr0 + mf * 16) * SSTR + kk * 2;
                ldsm4(aH[mf], addr);
                ldsm4(aL[mf], addr + TILEB);
            }
        }
        // B fragments (cols wn*64 .. +64): 4 x4-loads = 8 n8 frags, hi & lo
        uint32_t bH[4][4], bL[4][4];
        {
            int rbase = wn * 64 + ((lane >> 4) << 3) + (lane & 7);
            int kk    = ((lane >> 3) & 1) << 3;
            #pragma unroll
            for (int j = 0; j < 4; j++) {
                uint32_t addr = st + 2 * TILEB + (rbase + j * 16) * SSTR + kk * 2;
                ldsm4(bH[j], addr);
                ldsm4(bL[j], addr + TILEB);
            }
        }
        // 48 MMAs: hi*hi + hi*lo + lo*hi
        #pragma unroll
        for (int mf = 0; mf < 2; mf++)
            #pragma unroll
            for (int j = 0; j < 4; j++)
                #pragma unroll
                for (int hh = 0; hh < 2; hh++) {
                    float* d = acc[mf][j * 2 + hh];
                    mma16816(d, aH[mf], bH[j][2 * hh], bH[j][2 * hh + 1]);
                    mma16816(d, aH[mf], bL[j][2 * hh], bL[j][2 * hh + 1]);
                    mma16816(d, aL[mf], bH[j][2 * hh], bH[j][2 * hh + 1]);
                }
        __syncthreads();
    }

    // ---- epilogue: GLU. gate rows (64-127) -> smem, a rows apply sigmoid ----
    float* sg = (float*)smem;                 // [64][130] f32 = 33280 B
    const int r0 = (lane >> 2);
    const int c0 = (lane & 3) * 2;

    if (wm >= 2) {
        #pragma unroll
        for (int mf = 0; mf < 2; mf++) {
            int row = wm * 32 + mf * 16 + r0;     // 64..127
            int grow = row - 64;
            float bg = bias[H_ + h0 + grow];
            float bg2 = bias[H_ + h0 + grow + 8];
            #pragma unroll
            for (int nf = 0; nf < 8; nf++) {
                int col = wn * 64 + nf * 8 + c0;
                float2 v0 = make_float2(acc[mf][nf][0] + bg,  acc[mf][nf][1] + bg);
                float2 v1 = make_float2(acc[mf][nf][2] + bg2, acc[mf][nf][3] + bg2);
                *(float2*)&sg[grow * 130 + col]       = v0;
                *(float2*)&sg[(grow + 8) * 130 + col] = v1;
            }
        }
    }
    __syncthreads();
    if (wm < 2) {
        #pragma unroll
        for (int mf = 0; mf < 2; mf++) {
            int row = wm * 32 + mf * 16 + r0;     // 0..63
            int h  = h0 + row;
            float ba  = bias[h];
            float ba2 = bias[h + 8];
            float* ob  = out + ((size_t)b * H_ + h) * L_ + l0;
            float* ob2 = out + ((size_t)b * H_ + h + 8) * L_ + l0;
            #pragma unroll
            for (int nf = 0; nf < 8; nf++) {
                int col = wn * 64 + nf * 8 + c0;
                float2 g0 = *(const float2*)&sg[row * 130 + col];
                float2 g1 = *(const float2*)&sg[(row + 8) * 130 + col];
                float2 o0, o1;
                o0.x = (acc[mf][nf][0] + ba)  / (1.0f + expf(-g0.x));
                o0.y = (acc[mf][nf][1] + ba)  / (1.0f + expf(-g0.y));
                o1.x = (acc[mf][nf][2] + ba2) / (1.0f + expf(-g1.x));
                o1.y = (acc[mf][nf][3] + ba2) / (1.0f + expf(-g1.y));
                *(float2*)(ob  + col) = o0;
                *(float2*)(ob2 + col) = o1;
            }
        }
    }
}

// ---------------------------------------------------------------------------
extern "C" void kernel_launch(void* const* d_in, const int* in_sizes, int n_in,
                              void* d_out, int out_size)
{
    const float* u          = (const float*)d_in[0];
    const float* log_dt     = (const float*)d_in[1];
    const float* log_A_real = (const float*)d_in[2];
    const float* A_imag     = (const float*)d_in[3];
    const float* C          = (const float*)d_in[4];
    const float* D          = (const float*)d_in[5];
    const float* W_out      = (const float*)d_in[6];
    const float* b_out      = (const float*)d_in[7];
    float* out = (float*)d_out;

    prep_kernel<<<(HN + 127) / 128, 128>>>(log_dt, log_A_real, A_imag, C);
    wsplit_kernel<<<(O_ * H_ + 255) / 256, 256>>>(W_out);
    scan_kernel<<<(B_ * H_) / 4, 128>>>(u, D);

    dim3 grid(B_ * (L_ / 128), H_ / 64);     // (256, 8)
    gemm_glu_mma<<<grid, 256, SMEM_BYTES>>>(b_out, out);
}

// round 4
// speedup vs baseline: 1.6136x; 1.4203x over previous
#include <cuda_runtime.h>
#include <cuda_bf16.h>
#include <math.h>
#include <stdint.h>

#define B_ 8
#define H_ 512
#define L_ 4096
#define N_ 32
#define HN (H_ * N_)
#define O_ (2 * H_)

// ---------------- scratch (__device__ globals) -----------------------------
__device__ float d_wr[HN], d_wi[HN], d_csr[HN], d_csi[HN];
__device__ __nv_bfloat16 d_gTh[(size_t)B_ * L_ * H_];
__device__ __nv_bfloat16 d_gTl[(size_t)B_ * L_ * H_];
__device__ __nv_bfloat16 d_Wh[(size_t)O_ * H_];
__device__ __nv_bfloat16 d_Wl[(size_t)O_ * H_];

// ---------------------------------------------------------------------------
__device__ __forceinline__ uint32_t smem_u32(const void* p) {
    uint32_t a;
    asm("{ .reg .u64 t; cvta.to.shared.u64 t, %1; cvt.u32.u64 %0, t; }"
        : "=r"(a) : "l"(p));
    return a;
}

#define CP_ASYNC16(dst, src) \
    asm volatile("cp.async.cg.shared.global [%0], [%1], 16;" :: "r"(dst), "l"(src))
#define CP_COMMIT() asm volatile("cp.async.commit_group;" ::: "memory")
#define CP_WAIT1()  asm volatile("cp.async.wait_group 1;" ::: "memory")
#define CP_WAIT0()  asm volatile("cp.async.wait_group 0;" ::: "memory")

__device__ __forceinline__ void ldsm4(uint32_t* r, uint32_t addr) {
    asm volatile("ldmatrix.sync.aligned.m8n8.x4.shared.b16 {%0,%1,%2,%3}, [%4];"
                 : "=r"(r[0]), "=r"(r[1]), "=r"(r[2]), "=r"(r[3]) : "r"(addr));
}

__device__ __forceinline__ void mma16816(float* d, const uint32_t* a,
                                         uint32_t b0, uint32_t b1) {
    asm volatile("mma.sync.aligned.m16n8k16.row.col.f32.bf16.bf16.f32 "
                 "{%0,%1,%2,%3}, {%4,%5,%6,%7}, {%8,%9}, {%0,%1,%2,%3};"
                 : "+f"(d[0]), "+f"(d[1]), "+f"(d[2]), "+f"(d[3])
                 : "r"(a[0]), "r"(a[1]), "r"(a[2]), "r"(a[3]), "r"(b0), "r"(b1));
}

// ---------------------------------------------------------------------------
// Kernel 1: per (h,n) precompute  w = exp(dt*A),  2*Cs = 2*C*(w-1)/A
// ---------------------------------------------------------------------------
__global__ void prep_kernel(const float* __restrict__ log_dt,
                            const float* __restrict__ log_A_real,
                            const float* __restrict__ A_imag,
                            const float* __restrict__ C)
{
    int idx = blockIdx.x * blockDim.x + threadIdx.x;
    if (idx >= HN) return;
    int h = idx / N_;
    float dt = expf(log_dt[h]);
    float ar = -expf(log_A_real[idx]);
    float ai = A_imag[idx];
    float mag = expf(dt * ar);
    float wr = mag * cosf(dt * ai);
    float wi = mag * sinf(dt * ai);
    float den = ar * ar + ai * ai;
    float nr = wr - 1.0f, ni = wi;
    float qr = (nr * ar + ni * ai) / den;
    float qi = (ni * ar - nr * ai) / den;
    float Cr = C[2 * idx], Ci = C[2 * idx + 1];
    d_wr[idx]  = wr;
    d_wi[idx]  = wi;
    d_csr[idx] = 2.0f * (Cr * qr - Ci * qi);
    d_csi[idx] = 2.0f * (Cr * qi + Ci * qr);
}

// ---------------------------------------------------------------------------
// Kernel 1b: split W into bf16 hi/lo
// ---------------------------------------------------------------------------
__global__ void wsplit_kernel(const float* __restrict__ W)
{
    int idx = blockIdx.x * blockDim.x + threadIdx.x;
    if (idx >= O_ * H_) return;
    float w = W[idx];
    __nv_bfloat16 hi = __float2bfloat16(w);
    __nv_bfloat16 lo = __float2bfloat16(w - __bfloat162float(hi));
    d_Wh[idx] = hi;
    d_Wl[idx] = lo;
}

// ---------------------------------------------------------------------------
// Kernel 2: scan. 8 warps/block = 8 consecutive h of one b. Deferred
// cross-mode reduction via smem (1 shfl + 1 STS per step instead of 6 shfl),
// and smem transpose so gT stores are 16B-contiguous.
// ---------------------------------------------------------------------------
__global__ __launch_bounds__(256) void scan_kernel(const float* __restrict__ u,
                                                   const float* __restrict__ D)
{
    __shared__ float    red[8][32][33];   // [warp][t][lane]
    __shared__ uint32_t tr[8][36];        // packed (hi,lo) bf16 pair

    const int tid  = threadIdx.x;
    const int wid  = tid >> 5;
    const int lane = tid & 31;

    const int gw     = blockIdx.x * 8 + wid;   // global warp = (b,h)
    const int b      = gw >> 9;
    const int h      = gw & 511;
    const int h_base = (blockIdx.x * 8) & 511; // first h of this block

    const int idx = h * N_ + lane;
    const float wr = d_wr[idx], wi = d_wi[idx];
    const float cr = d_csr[idx], nci = -d_csi[idx];
    const float Dh = D[h];

    const float* up = u + ((size_t)b * H_ + h) * L_;
    const size_t obase = (size_t)b * L_ * H_ + h_base;

    // store-phase mapping
    const int sl = tid >> 3;        // l within group (0..31)
    const int sh = tid & 7;         // h column (0..7)

    float xr = 0.0f, xi = 0.0f;

    for (int l0 = 0; l0 < L_; l0 += 32) {
        float uv = up[l0 + lane];
        #pragma unroll
        for (int t = 0; t < 32; t++) {
            float ut = __shfl_sync(0xffffffffu, uv, t);
            float t0  = fmaf(-wi, xi, ut);
            float t1  = wi * xr;
            float nxr = fmaf(wr, xr, t0);
            float nxi = fmaf(wr, xi, t1);
            xr = nxr; xi = nxi;
            red[wid][t][lane] = fmaf(cr, xr, nci * xi);
        }
        __syncwarp();
        // lane t sums the 32 mode-contributions for timestep t
        float s0 = 0.0f, s1 = 0.0f, s2 = 0.0f, s3 = 0.0f;
        #pragma unroll
        for (int j = 0; j < 32; j += 4) {
            s0 += red[wid][lane][j + 0];
            s1 += red[wid][lane][j + 1];
            s2 += red[wid][lane][j + 2];
            s3 += red[wid][lane][j + 3];
        }
        float y = fmaf(Dh, uv, (s0 + s1) + (s2 + s3));   // uv = u at t=lane
        float gv = 0.5f * y * (1.0f + erff(y * 0.70710678118654752f));
        __nv_bfloat16 hi = __float2bfloat16(gv);
        __nv_bfloat16 lo = __float2bfloat16(gv - __bfloat162float(hi));
        tr[wid][lane] = (uint32_t)__bfloat16_as_ushort(hi) |
                        ((uint32_t)__bfloat16_as_ushort(lo) << 16);
        __syncthreads();
        {
            uint32_t v = tr[sh][sl];
            size_t o = obase + (size_t)(l0 + sl) * H_ + sh;
            d_gTh[o] = __ushort_as_bfloat16((unsigned short)(v & 0xffffu));
            d_gTl[o] = __ushort_as_bfloat16((unsigned short)(v >> 16));
        }
        __syncthreads();
    }
}

// ---------------------------------------------------------------------------
// Kernel 3: mma.sync bf16 split GEMM + GLU.
// CTA: M=128 (rows 0-63 = a-channels h0.., rows 64-127 = gate channels
// 512+h0..), N=64 l-cols, BK=16 double-buffered cp.async.
// 8 warps (4M x 2N), warp tile 32x32. 2 CTAs/SM.
// ---------------------------------------------------------------------------
#define BK 16
#define SSTR 48
#define TILE_A 6144                 // 128 * 48
#define TILE_Bs 3072                // 64 * 48
#define OFF_AH 0
#define OFF_AL TILE_A
#define OFF_BH (2 * TILE_A)
#define OFF_BL (2 * TILE_A + TILE_Bs)
#define STAGEB (2 * TILE_A + 2 * TILE_Bs)   // 18432
#define SMEM_BYTES (2 * STAGEB)             // 36864
#define NSTAGE (H_ / BK)                    // 32

__global__ __launch_bounds__(256, 2) void gemm_glu_mma(const float* __restrict__ bias,
                                                       float* __restrict__ out)
{
    extern __shared__ char smem[];
    const int tid  = threadIdx.x;
    const int wid  = tid >> 5;
    const int lane = tid & 31;

    const int b  = blockIdx.x >> 6;
    const int l0 = (blockIdx.x & 63) * 64;
    const int h0 = blockIdx.y * 64;

    const uint32_t sb = smem_u32(smem);

    // ---- cp.async mapping: 3 x 16B per thread per stage (768 txns) ----
    const char* srcs[3];
    uint32_t    dsts[3];
    #pragma unroll
    for (int j = 0; j < 3; j++) {
        int id = tid + 256 * j;
        const __nv_bfloat16* base;
        size_t rowoff;
        uint32_t dst;
        if (id < 512) {
            int tile = id >> 8;               // 0=Ah 1=Al
            int rem  = id & 255;
            int r    = rem >> 1;
            int seg  = rem & 1;
            int arow = h0 + r + ((r >= 64) ? 448 : 0);
            base   = (tile == 0) ? d_Wh : d_Wl;
            rowoff = (size_t)arow * H_;
            dst    = sb + tile * TILE_A + r * SSTR + seg * 16;
            srcs[j] = (const char*)(base + rowoff) + seg * 16;
            dsts[j] = dst;
        } else {
            int idb  = id - 512;
            int tile = idb >> 7;              // 0=Bh 1=Bl
            int rem  = idb & 127;
            int r    = rem >> 1;
            int seg  = rem & 1;
            base   = ((tile == 0) ? d_gTh : d_gTl) + (size_t)b * L_ * H_;
            rowoff = (size_t)(l0 + r) * H_;
            dst    = sb + OFF_BH + tile * TILE_Bs + r * SSTR + seg * 16;
            srcs[j] = (const char*)(base + rowoff) + seg * 16;
            dsts[j] = dst;
        }
    }

    #pragma unroll
    for (int j = 0; j < 3; j++) CP_ASYNC16(dsts[j], srcs[j]);
    CP_COMMIT();

    float acc[2][4][4];
    #pragma unroll
    for (int mf = 0; mf < 2; mf++)
        #pragma unroll
        for (int nf = 0; nf < 4; nf++)
            #pragma unroll
            for (int e = 0; e < 4; e++) acc[mf][nf][e] = 0.0f;

    const int wm = wid >> 1;    // 0..3
    const int wn = wid & 1;     // 0..1

    for (int s = 0; s < NSTAGE; s++) {
        if (s + 1 < NSTAGE) {
            uint32_t dbo = ((s + 1) & 1) * STAGEB;
            size_t   sbo = (size_t)(s + 1) * (BK * 2);
            #pragma unroll
            for (int j = 0; j < 3; j++) CP_ASYNC16(dsts[j] + dbo, srcs[j] + sbo);
            CP_COMMIT();
            CP_WAIT1();
        } else {
            CP_WAIT0();
        }
        __syncthreads();

        const uint32_t st = sb + (s & 1) * STAGEB;

        uint32_t aH[2][4], aL[2][4];
        {
            int rr0 = wm * 32 + (lane & 15);
            int kk  = ((lane >> 4) << 3) * 2;
            #pragma unroll
            for (int mf = 0; mf < 2; mf++) {
                uint32_t addr = st + OFF_AH + (rr0 + mf * 16) * SSTR + kk;
                ldsm4(aH[mf], addr);
                ldsm4(aL[mf], addr + TILE_A);
            }
        }
        uint32_t bH[2][4], bL[2][4];
        {
            int rbase = wn * 32 + ((lane >> 4) << 3) + (lane & 7);
            int kk    = (((lane >> 3) & 1) << 3) * 2;
            #pragma unroll
            for (int jb = 0; jb < 2; jb++) {
                uint32_t addr = st + OFF_BH + (rbase + jb * 16) * SSTR + kk;
                ldsm4(bH[jb], addr);
                ldsm4(bL[jb], addr + TILE_Bs);
            }
        }
        #pragma unroll
        for (int mf = 0; mf < 2; mf++)
            #pragma unroll
            for (int jb = 0; jb < 2; jb++)
                #pragma unroll
                for (int hh = 0; hh < 2; hh++) {
                    float* d = acc[mf][jb * 2 + hh];
                    mma16816(d, aH[mf], bH[jb][2 * hh], bH[jb][2 * hh + 1]);
                    mma16816(d, aH[mf], bL[jb][2 * hh], bL[jb][2 * hh + 1]);
                    mma16816(d, aL[mf], bH[jb][2 * hh], bH[jb][2 * hh + 1]);
                }
        __syncthreads();
    }

    // ---- epilogue: GLU ----
    float* sg = (float*)smem;               // [64][66] f32
    const int r0 = (lane >> 2);
    const int c0 = (lane & 3) * 2;

    if (wm >= 2) {
        #pragma unroll
        for (int mf = 0; mf < 2; mf++) {
            int row = wm * 32 + mf * 16 + r0;     // 64..127
            int grow = row - 64;
            float bg  = bias[H_ + h0 + grow];
            float bg2 = bias[H_ + h0 + grow + 8];
            #pragma unroll
            for (int nf = 0; nf < 4; nf++) {
                int col = wn * 32 + nf * 8 + c0;
                *(float2*)&sg[grow * 66 + col] =
                    make_float2(acc[mf][nf][0] + bg, acc[mf][nf][1] + bg);
                *(float2*)&sg[(grow + 8) * 66 + col] =
                    make_float2(acc[mf][nf][2] + bg2, acc[mf][nf][3] + bg2);
            }
        }
    }
    __syncthreads();
    if (wm < 2) {
        #pragma unroll
        for (int mf = 0; mf < 2; mf++) {
            int row = wm * 32 + mf * 16 + r0;     // 0..63
            int h  = h0 + row;
            float ba  = bias[h];
            float ba2 = bias[h + 8];
            float* ob  = out + ((size_t)b * H_ + h) * L_ + l0;
            float* ob2 = out + ((size_t)b * H_ + h + 8) * L_ + l0;
            #pragma unroll
            for (int nf = 0; nf < 4; nf++) {
                int col = wn * 32 + nf * 8 + c0;
                float2 g0 = *(const float2*)&sg[row * 66 + col];
                float2 g1 = *(const float2*)&sg[(row + 8) * 66 + col];
                float2 o0, o1;
                o0.x = (acc[mf][nf][0] + ba)  / (1.0f + expf(-g0.x));
                o0.y = (acc[mf][nf][1] + ba)  / (1.0f + expf(-g0.y));
                o1.x = (acc[mf][nf][2] + ba2) / (1.0f + expf(-g1.x));
                o1.y = (acc[mf][nf][3] + ba2) / (1.0f + expf(-g1.y));
                *(float2*)(ob  + col) = o0;
                *(float2*)(ob2 + col) = o1;
            }
        }
    }
}

// ---------------------------------------------------------------------------
extern "C" void kernel_launch(void* const* d_in, const int* in_sizes, int n_in,
                              void* d_out, int out_size)
{
    const float* u          = (const float*)d_in[0];
    const float* log_dt     = (const float*)d_in[1];
    const float* log_A_real = (const float*)d_in[2];
    const float* A_imag     = (const float*)d_in[3];
    const float* C          = (const float*)d_in[4];
    const float* D          = (const float*)d_in[5];
    const float* W_out      = (const float*)d_in[6];
    const float* b_out      = (const float*)d_in[7];
    float* out = (float*)d_out;

    prep_kernel<<<(HN + 127) / 128, 128>>>(log_dt, log_A_real, A_imag, C);
    wsplit_kernel<<<(O_ * H_ + 255) / 256, 256>>>(W_out);
    scan_kernel<<<(B_ * H_) / 8, 256>>>(u, D);

    dim3 grid(B_ * (L_ / 64), H_ / 64);     // (512, 8)
    gemm_glu_mma<<<grid, 256, SMEM_BYTES>>>(b_out, out);
}

// round 5
// speedup vs baseline: 1.7248x; 1.0689x over previous
#include <cuda_runtime.h>
#include <cuda_bf16.h>
#include <math.h>
#include <stdint.h>

#define B_ 8
#define H_ 512
#define L_ 4096
#define N_ 32
#define HN (H_ * N_)
#define O_ (2 * H_)

// ---------------- scratch (__device__ globals) -----------------------------
__device__ float d_wr[HN], d_wi[HN], d_csr[HN], d_csi[HN];
__device__ __nv_bfloat16 d_gTh[(size_t)B_ * L_ * H_];
__device__ __nv_bfloat16 d_gTl[(size_t)B_ * L_ * H_];
__device__ __nv_bfloat16 d_Wh[(size_t)O_ * H_];
__device__ __nv_bfloat16 d_Wl[(size_t)O_ * H_];

// ---------------------------------------------------------------------------
__device__ __forceinline__ uint32_t smem_u32(const void* p) {
    uint32_t a;
    asm("{ .reg .u64 t; cvta.to.shared.u64 t, %1; cvt.u32.u64 %0, t; }"
        : "=r"(a) : "l"(p));
    return a;
}

#define CP_ASYNC16(dst, src) \
    asm volatile("cp.async.cg.shared.global [%0], [%1], 16;" :: "r"(dst), "l"(src))
#define CP_COMMIT() asm volatile("cp.async.commit_group;" ::: "memory")
#define CP_WAIT1()  asm volatile("cp.async.wait_group 1;" ::: "memory")
#define CP_WAIT0()  asm volatile("cp.async.wait_group 0;" ::: "memory")

__device__ __forceinline__ void ldsm4(uint32_t* r, uint32_t addr) {
    asm volatile("ldmatrix.sync.aligned.m8n8.x4.shared.b16 {%0,%1,%2,%3}, [%4];"
                 : "=r"(r[0]), "=r"(r[1]), "=r"(r[2]), "=r"(r[3]) : "r"(addr));
}

__device__ __forceinline__ void mma16816(float* d, const uint32_t* a,
                                         uint32_t b0, uint32_t b1) {
    asm volatile("mma.sync.aligned.m16n8k16.row.col.f32.bf16.bf16.f32 "
                 "{%0,%1,%2,%3}, {%4,%5,%6,%7}, {%8,%9}, {%0,%1,%2,%3};"
                 : "+f"(d[0]), "+f"(d[1]), "+f"(d[2]), "+f"(d[3])
                 : "r"(a[0]), "r"(a[1]), "r"(a[2]), "r"(a[3]), "r"(b0), "r"(b1));
}

// ---------------------------------------------------------------------------
// Kernel 1: per (h,n) precompute  w = exp(dt*A),  2*Cs = 2*C*(w-1)/A
// ---------------------------------------------------------------------------
__global__ void prep_kernel(const float* __restrict__ log_dt,
                            const float* __restrict__ log_A_real,
                            const float* __restrict__ A_imag,
                            const float* __restrict__ C)
{
    int idx = blockIdx.x * blockDim.x + threadIdx.x;
    if (idx >= HN) return;
    int h = idx / N_;
    float dt = expf(log_dt[h]);
    float ar = -expf(log_A_real[idx]);
    float ai = A_imag[idx];
    float mag = expf(dt * ar);
    float wr = mag * cosf(dt * ai);
    float wi = mag * sinf(dt * ai);
    float den = ar * ar + ai * ai;
    float nr = wr - 1.0f, ni = wi;
    float qr = (nr * ar + ni * ai) / den;
    float qi = (ni * ar - nr * ai) / den;
    float Cr = C[2 * idx], Ci = C[2 * idx + 1];
    d_wr[idx]  = wr;
    d_wi[idx]  = wi;
    d_csr[idx] = 2.0f * (Cr * qr - Ci * qi);
    d_csi[idx] = 2.0f * (Cr * qi + Ci * qr);
}

// ---------------------------------------------------------------------------
// Kernel 1b: split W into bf16 hi/lo
// ---------------------------------------------------------------------------
__global__ void wsplit_kernel(const float* __restrict__ W)
{
    int idx = blockIdx.x * blockDim.x + threadIdx.x;
    if (idx >= O_ * H_) return;
    float w = W[idx];
    __nv_bfloat16 hi = __float2bfloat16(w);
    __nv_bfloat16 lo = __float2bfloat16(w - __bfloat162float(hi));
    d_Wh[idx] = hi;
    d_Wl[idx] = lo;
}

// ---------------------------------------------------------------------------
// Kernel 2: scan. 8 warps/block = 8 consecutive h of one b.
// Per step: 2 butterfly shfl rounds -> 8 partials, lanes 0-7 store to smem.
// Per 32-step group: lane t sums its 8 partials, GELU, smem transpose,
// 16B-contiguous bf16 hi/lo stores. One barrier per group (tr double-buffered).
// ---------------------------------------------------------------------------
__global__ __launch_bounds__(256) void scan_kernel(const float* __restrict__ u,
                                                   const float* __restrict__ D)
{
    __shared__ float    red[8][32][9];    // [warp][t][partial]
    __shared__ uint32_t tr[2][8][36];     // double-buffered transpose staging

    const int tid  = threadIdx.x;
    const int wid  = tid >> 5;
    const int lane = tid & 31;

    const int gw     = blockIdx.x * 8 + wid;
    const int b      = gw >> 9;
    const int h      = gw & 511;
    const int h_base = (blockIdx.x * 8) & 511;

    const int idx = h * N_ + lane;
    const float wr = d_wr[idx], wi = d_wi[idx];
    const float cr = d_csr[idx], nci = -d_csi[idx];
    const float Dh = D[h];

    const float* up = u + ((size_t)b * H_ + h) * L_;
    const size_t obase = (size_t)b * L_ * H_ + h_base;

    const int sl = tid >> 3;        // l within group (0..31)
    const int sh = tid & 7;         // h column (0..7)

    float xr = 0.0f, xi = 0.0f;

    for (int l0 = 0; l0 < L_; l0 += 32) {
        const int p = (l0 >> 5) & 1;
        float uv = up[l0 + lane];
        #pragma unroll
        for (int t = 0; t < 32; t++) {
            float ut = __shfl_sync(0xffffffffu, uv, t);
            float t0  = fmaf(-wi, xi, ut);
            float t1  = wi * xr;
            float nxr = fmaf(wr, xr, t0);
            float nxi = fmaf(wr, xi, t1);
            xr = nxr; xi = nxi;
            float c = fmaf(cr, xr, nci * xi);
            c += __shfl_xor_sync(0xffffffffu, c, 16);
            c += __shfl_xor_sync(0xffffffffu, c, 8);
            if (lane < 8) red[wid][t][lane] = c;
        }
        __syncwarp();
        // lane t sums the 8 partials for timestep t
        float s = ((red[wid][lane][0] + red[wid][lane][1]) +
                   (red[wid][lane][2] + red[wid][lane][3])) +
                  ((red[wid][lane][4] + red[wid][lane][5]) +
                   (red[wid][lane][6] + red[wid][lane][7]));
        float y = fmaf(Dh, uv, s);                 // uv = u at t=lane
        float gv = 0.5f * y * (1.0f + erff(y * 0.70710678118654752f));
        __nv_bfloat16 hi = __float2bfloat16(gv);
        __nv_bfloat16 lo = __float2bfloat16(gv - __bfloat162float(hi));
        tr[p][wid][lane] = (uint32_t)__bfloat16_as_ushort(hi) |
                           ((uint32_t)__bfloat16_as_ushort(lo) << 16);
        __syncthreads();
        {
            uint32_t v = tr[p][sh][sl];
            size_t o = obase + (size_t)(l0 + sl) * H_ + sh;
            d_gTh[o] = __ushort_as_bfloat16((unsigned short)(v & 0xffffu));
            d_gTl[o] = __ushort_as_bfloat16((unsigned short)(v >> 16));
        }
    }
}

// ---------------------------------------------------------------------------
// Kernel 3: mma.sync bf16 split GEMM + GLU.
// CTA: M=128 (rows 0-63 = a-channels h0.., rows 64-127 = gate channels
// 512+h0..), N=64 l-cols, BK=32, 3-stage cp.async pipeline, one barrier/stage.
// 8 warps (4M x 2N), warp tile 32x32, 2 CTAs/SM.
// ---------------------------------------------------------------------------
#define BK 32
#define SSTR 80                     // 64B data + 16B pad (conflict-free mod 128)
#define TILE_A 10240                // 128 * 80
#define TILE_Bs 5120                // 64 * 80
#define OFF_BH (2 * TILE_A)
#define STAGEB (2 * TILE_A + 2 * TILE_Bs)   // 30720
#define NSTAGE (H_ / BK)                    // 16
#define SMEM_BYTES (3 * STAGEB)             // 92160

__global__ __launch_bounds__(256, 2) void gemm_glu_mma(const float* __restrict__ bias,
                                                       float* __restrict__ out)
{
    extern __shared__ char smem[];
    const int tid  = threadIdx.x;
    const int wid  = tid >> 5;
    const int lane = tid & 31;

    const int b  = blockIdx.x >> 6;
    const int l0 = (blockIdx.x & 63) * 64;
    const int h0 = blockIdx.y * 64;

    const uint32_t sb = smem_u32(smem);

    // ---- cp.async mapping: 6 x 16B per thread per stage (1536 txns) ----
    const char* srcs[6];
    uint32_t    dsts[6];
    #pragma unroll
    for (int j = 0; j < 6; j++) {
        int id = tid + 256 * j;
        if (id < 1024) {
            int plane = id >> 9;              // 0=Wh 1=Wl
            int rem   = id & 511;
            int row   = rem >> 2;             // 0..127
            int seg   = rem & 3;
            int arow  = h0 + row + ((row >= 64) ? 448 : 0);
            const __nv_bfloat16* base = plane ? d_Wl : d_Wh;
            srcs[j] = (const char*)(base + (size_t)arow * H_) + seg * 16;
            dsts[j] = sb + plane * TILE_A + row * SSTR + seg * 16;
        } else {
            int idb   = id - 1024;
            int plane = idb >> 8;             // 0=gh 1=gl
            int rem   = idb & 255;
            int row   = rem >> 2;             // 0..63
            int seg   = rem & 3;
            const __nv_bfloat16* base =
                (plane ? d_gTl : d_gTh) + (size_t)b * L_ * H_;
            srcs[j] = (const char*)(base + (size_t)(l0 + row) * H_) + seg * 16;
            dsts[j] = sb + OFF_BH + plane * TILE_Bs + row * SSTR + seg * 16;
        }
    }

    // prologue: stages 0 and 1
    #pragma unroll
    for (int j = 0; j < 6; j++) CP_ASYNC16(dsts[j], srcs[j]);
    CP_COMMIT();
    #pragma unroll
    for (int j = 0; j < 6; j++) CP_ASYNC16(dsts[j] + STAGEB, srcs[j] + 64);
    CP_COMMIT();

    float acc[2][4][4];
    #pragma unroll
    for (int mf = 0; mf < 2; mf++)
        #pragma unroll
        for (int nf = 0; nf < 4; nf++)
            #pragma unroll
            for (int e = 0; e < 4; e++) acc[mf][nf][e] = 0.0f;

    const int wm = wid >> 1;
    const int wn = wid & 1;

    for (int s = 0; s < NSTAGE; s++) {
        if (s == NSTAGE - 1) { CP_WAIT0(); } else { CP_WAIT1(); }
        __syncthreads();

        const uint32_t st = sb + (uint32_t)(s % 3) * STAGEB;

        #pragma unroll
        for (int ks = 0; ks < 2; ks++) {
            uint32_t aH[2][4], aL[2][4];
            {
                int rr0 = wm * 32 + (lane & 15);
                int kb  = ks * 32 + ((lane >> 4) << 4);
                #pragma unroll
                for (int mf = 0; mf < 2; mf++) {
                    uint32_t addr = st + (rr0 + mf * 16) * SSTR + kb;
                    ldsm4(aH[mf], addr);
                    ldsm4(aL[mf], addr + TILE_A);
                }
            }
            uint32_t bH[2][4], bL[2][4];
            {
                int rbase = wn * 32 + ((lane >> 4) << 3) + (lane & 7);
                int kb    = ks * 32 + (((lane >> 3) & 1) << 4);
                #pragma unroll
                for (int jb = 0; jb < 2; jb++) {
                    uint32_t addr = st + OFF_BH + (rbase + jb * 16) * SSTR + kb;
                    ldsm4(bH[jb], addr);
                    ldsm4(bL[jb], addr + TILE_Bs);
                }
            }
            #pragma unroll
            for (int mf = 0; mf < 2; mf++)
                #pragma unroll
                for (int jb = 0; jb < 2; jb++)
                    #pragma unroll
                    for (int hh = 0; hh < 2; hh++) {
                        float* d = acc[mf][jb * 2 + hh];
                        mma16816(d, aH[mf], bH[jb][2 * hh], bH[jb][2 * hh + 1]);
                        mma16816(d, aH[mf], bL[jb][2 * hh], bL[jb][2 * hh + 1]);
                        mma16816(d, aL[mf], bH[jb][2 * hh], bH[jb][2 * hh + 1]);
                    }
        }

        if (s + 2 < NSTAGE) {
            uint32_t dbo = (uint32_t)((s + 2) % 3) * STAGEB;
            size_t   sbo = (size_t)(s + 2) * 64;
            #pragma unroll
            for (int j = 0; j < 6; j++) CP_ASYNC16(dsts[j] + dbo, srcs[j] + sbo);
            CP_COMMIT();
        }
    }
    __syncthreads();   // before smem reuse in epilogue

    // ---- epilogue: GLU ----
    float* sg = (float*)smem;               // [64][66] f32
    const int r0 = (lane >> 2);
    const int c0 = (lane & 3) * 2;

    if (wm >= 2) {
        #pragma unroll
        for (int mf = 0; mf < 2; mf++) {
            int row = wm * 32 + mf * 16 + r0;     // 64..127
            int grow = row - 64;
            float bg  = bias[H_ + h0 + grow];
            float bg2 = bias[H_ + h0 + grow + 8];
            #pragma unroll
            for (int nf = 0; nf < 4; nf++) {
                int col = wn * 32 + nf * 8 + c0;
                *(float2*)&sg[grow * 66 + col] =
                    make_float2(acc[mf][nf][0] + bg, acc[mf][nf][1] + bg);
                *(float2*)&sg[(grow + 8) * 66 + col] =
                    make_float2(acc[mf][nf][2] + bg2, acc[mf][nf][3] + bg2);
            }
        }
    }
    __syncthreads();
    if (wm < 2) {
        #pragma unroll
        for (int mf = 0; mf < 2; mf++) {
            int row = wm * 32 + mf * 16 + r0;     // 0..63
            int h  = h0 + row;
            float ba  = bias[h];
            float ba2 = bias[h + 8];
            float* ob  = out + ((size_t)b * H_ + h) * L_ + l0;
            float* ob2 = out + ((size_t)b * H_ + h + 8) * L_ + l0;
            #pragma unroll
            for (int nf = 0; nf < 4; nf++) {
                int col = wn * 32 + nf * 8 + c0;
                float2 g0 = *(const float2*)&sg[row * 66 + col];
                float2 g1 = *(const float2*)&sg[(row + 8) * 66 + col];
                float2 o0, o1;
                o0.x = (acc[mf][nf][0] + ba)  / (1.0f + expf(-g0.x));
                o0.y = (acc[mf][nf][1] + ba)  / (1.0f + expf(-g0.y));
                o1.x = (acc[mf][nf][2] + ba2) / (1.0f + expf(-g1.x));
                o1.y = (acc[mf][nf][3] + ba2) / (1.0f + expf(-g1.y));
                *(float2*)(ob  + col) = o0;
                *(float2*)(ob2 + col) = o1;
            }
        }
    }
}

// ---------------------------------------------------------------------------
extern "C" void kernel_launch(void* const* d_in, const int* in_sizes, int n_in,
                              void* d_out, int out_size)
{
    const float* u          = (const float*)d_in[0];
    const float* log_dt     = (const float*)d_in[1];
    const float* log_A_real = (const float*)d_in[2];
    const float* A_imag     = (const float*)d_in[3];
    const float* C          = (const float*)d_in[4];
    const float* D          = (const float*)d_in[5];
    const float* W_out      = (const float*)d_in[6];
    const float* b_out      = (const float*)d_in[7];
    float* out = (float*)d_out;

    static bool attr_set = false;
    if (!attr_set) {
        cudaFuncSetAttribute(gemm_glu_mma, cudaFuncAttributeMaxDynamicSharedMemorySize,
                             SMEM_BYTES);
        attr_set = true;
    }

    prep_kernel<<<(HN + 127) / 128, 128>>>(log_dt, log_A_real, A_imag, C);
    wsplit_kernel<<<(O_ * H_ + 255) / 256, 256>>>(W_out);
    scan_kernel<<<(B_ * H_) / 8, 256>>>(u, D);

    dim3 grid(B_ * (L_ / 64), H_ / 64);     // (512, 8)
    gemm_glu_mma<<<grid, 256, SMEM_BYTES>>>(b_out, out);
}

// round 6
// speedup vs baseline: 1.8695x; 1.0839x over previous
#include <cuda_runtime.h>
#include <cuda_bf16.h>
#include <math.h>
#include <stdint.h>

#define B_ 8
#define H_ 512
#define L_ 4096
#define N_ 32
#define HN (H_ * N_)
#define O_ (2 * H_)

// ---------------- scratch (__device__ globals) -----------------------------
__device__ float d_wr[HN], d_wi[HN], d_csr[HN], d_csi[HN];
__device__ __nv_bfloat16 d_gTh[(size_t)B_ * L_ * H_];
__device__ __nv_bfloat16 d_gTl[(size_t)B_ * L_ * H_];
__device__ __nv_bfloat16 d_Wh[(size_t)O_ * H_];
__device__ __nv_bfloat16 d_Wl[(size_t)O_ * H_];

// ---------------------------------------------------------------------------
__device__ __forceinline__ uint32_t smem_u32(const void* p) {
    uint32_t a;
    asm("{ .reg .u64 t; cvta.to.shared.u64 t, %1; cvt.u32.u64 %0, t; }"
        : "=r"(a) : "l"(p));
    return a;
}

#define CP_ASYNC16(dst, src) \
    asm volatile("cp.async.cg.shared.global [%0], [%1], 16;" :: "r"(dst), "l"(src))
#define CP_COMMIT() asm volatile("cp.async.commit_group;" ::: "memory")
#define CP_WAIT1()  asm volatile("cp.async.wait_group 1;" ::: "memory")
#define CP_WAIT0()  asm volatile("cp.async.wait_group 0;" ::: "memory")

__device__ __forceinline__ void ldsm4(uint32_t* r, uint32_t addr) {
    asm volatile("ldmatrix.sync.aligned.m8n8.x4.shared.b16 {%0,%1,%2,%3}, [%4];"
                 : "=r"(r[0]), "=r"(r[1]), "=r"(r[2]), "=r"(r[3]) : "r"(addr));
}

__device__ __forceinline__ void mma16816(float* d, const uint32_t* a,
                                         uint32_t b0, uint32_t b1) {
    asm volatile("mma.sync.aligned.m16n8k16.row.col.f32.bf16.bf16.f32 "
                 "{%0,%1,%2,%3}, {%4,%5,%6,%7}, {%8,%9}, {%0,%1,%2,%3};"
                 : "+f"(d[0]), "+f"(d[1]), "+f"(d[2]), "+f"(d[3])
                 : "r"(a[0]), "r"(a[1]), "r"(a[2]), "r"(a[3]), "r"(b0), "r"(b1));
}

// ---------------------------------------------------------------------------
// Kernel 1: per (h,n) precompute  w = exp(dt*A),  2*Cs = 2*C*(w-1)/A
// ---------------------------------------------------------------------------
__global__ void prep_kernel(const float* __restrict__ log_dt,
                            const float* __restrict__ log_A_real,
                            const float* __restrict__ A_imag,
                            const float* __restrict__ C)
{
    int idx = blockIdx.x * blockDim.x + threadIdx.x;
    if (idx >= HN) return;
    int h = idx / N_;
    float dt = expf(log_dt[h]);
    float ar = -expf(log_A_real[idx]);
    float ai = A_imag[idx];
    float mag = expf(dt * ar);
    float wr = mag * cosf(dt * ai);
    float wi = mag * sinf(dt * ai);
    float den = ar * ar + ai * ai;
    float nr = wr - 1.0f, ni = wi;
    float qr = (nr * ar + ni * ai) / den;
    float qi = (ni * ar - nr * ai) / den;
    float Cr = C[2 * idx], Ci = C[2 * idx + 1];
    d_wr[idx]  = wr;
    d_wi[idx]  = wi;
    d_csr[idx] = 2.0f * (Cr * qr - Ci * qi);
    d_csi[idx] = 2.0f * (Cr * qi + Ci * qr);
}

// ---------------------------------------------------------------------------
// Kernel 1b: split W into bf16 hi/lo
// ---------------------------------------------------------------------------
__global__ void wsplit_kernel(const float* __restrict__ W)
{
    int idx = blockIdx.x * blockDim.x + threadIdx.x;
    if (idx >= O_ * H_) return;
    float w = W[idx];
    __nv_bfloat16 hi = __float2bfloat16(w);
    __nv_bfloat16 lo = __float2bfloat16(w - __bfloat162float(hi));
    d_Wh[idx] = hi;
    d_Wl[idx] = lo;
}

// ---------------------------------------------------------------------------
// Kernel 2: scan. 8 warps/block = 8 consecutive h of one b.
// Per step: 1 shfl broadcast + 4 FMA + 1 STS (full deferred reduction).
// Per 32-step group: lane t column-sums 32 contributions, GELU, smem
// transpose, 16B-contiguous bf16 hi/lo stores. One barrier per group
// (double-buffered tr).
// ---------------------------------------------------------------------------
__global__ __launch_bounds__(256) void scan_kernel(const float* __restrict__ u,
                                                   const float* __restrict__ D)
{
    __shared__ float    red[8][32][33];   // [warp][t][lane]
    __shared__ uint32_t tr[2][8][36];     // double-buffered transpose staging

    const int tid  = threadIdx.x;
    const int wid  = tid >> 5;
    const int lane = tid & 31;

    const int gw     = blockIdx.x * 8 + wid;
    const int b      = gw >> 9;
    const int h      = gw & 511;
    const int h_base = (blockIdx.x * 8) & 511;

    const int idx = h * N_ + lane;
    const float wr = d_wr[idx], wi = d_wi[idx];
    const float cr = d_csr[idx], nci = -d_csi[idx];
    const float Dh = D[h];

    const float* up = u + ((size_t)b * H_ + h) * L_;
    const size_t obase = (size_t)b * L_ * H_ + h_base;

    const int sl = tid >> 3;        // l within group (0..31)
    const int sh = tid & 7;         // h column (0..7)

    float xr = 0.0f, xi = 0.0f;

    for (int l0 = 0; l0 < L_; l0 += 32) {
        const int p = (l0 >> 5) & 1;
        float uv = up[l0 + lane];
        #pragma unroll
        for (int t = 0; t < 32; t++) {
            float ut = __shfl_sync(0xffffffffu, uv, t);
            float t0  = fmaf(-wi, xi, ut);
            float t1  = wi * xr;
            float nxr = fmaf(wr, xr, t0);
            float nxi = fmaf(wr, xi, t1);
            xr = nxr; xi = nxi;
            red[wid][t][lane] = fmaf(cr, xr, nci * xi);
        }
        __syncwarp();
        // lane t sums the 32 mode-contributions for timestep t
        float s0 = 0.0f, s1 = 0.0f, s2 = 0.0f, s3 = 0.0f;
        #pragma unroll
        for (int j = 0; j < 32; j += 4) {
            s0 += red[wid][lane][j + 0];
            s1 += red[wid][lane][j + 1];
            s2 += red[wid][lane][j + 2];
            s3 += red[wid][lane][j + 3];
        }
        float y = fmaf(Dh, uv, (s0 + s1) + (s2 + s3));   // uv = u at t=lane
        float gv = 0.5f * y * (1.0f + erff(y * 0.70710678118654752f));
        __nv_bfloat16 hi = __float2bfloat16(gv);
        __nv_bfloat16 lo = __float2bfloat16(gv - __bfloat162float(hi));
        tr[p][wid][lane] = (uint32_t)__bfloat16_as_ushort(hi) |
                           ((uint32_t)__bfloat16_as_ushort(lo) << 16);
        __syncthreads();
        {
            uint32_t v = tr[p][sh][sl];
            size_t o = obase + (size_t)(l0 + sl) * H_ + sh;
            d_gTh[o] = __ushort_as_bfloat16((unsigned short)(v & 0xffffu));
            d_gTl[o] = __ushort_as_bfloat16((unsigned short)(v >> 16));
        }
    }
}

// ---------------------------------------------------------------------------
// Kernel 3: mma.sync bf16 split GEMM + GLU.
// CTA: M=128 (rows 0-63 = a-channels h0.., rows 64-127 = gate channels
// 512+h0..), N=64 l-cols, BK=32, 3-stage cp.async pipeline.
// 8 warps (4M x 2N), warp tile 32x32, 2 CTAs/SM.
// Hoisted ldsm offsets; MMAs issued in 3 split-passes (independent d-chains).
// ---------------------------------------------------------------------------
#define BK 32
#define SSTR 80
#define TILE_A 10240
#define TILE_Bs 5120
#define OFF_BH (2 * TILE_A)
#define STAGEB (2 * TILE_A + 2 * TILE_Bs)   // 30720
#define NSTAGE (H_ / BK)                    // 16
#define SMEM_BYTES (3 * STAGEB)             // 92160

__global__ __launch_bounds__(256, 2) void gemm_glu_mma(const float* __restrict__ bias,
                                                       float* __restrict__ out)
{
    extern __shared__ char smem[];
    const int tid  = threadIdx.x;
    const int wid  = tid >> 5;
    const int lane = tid & 31;

    const int b  = blockIdx.x >> 6;
    const int l0 = (blockIdx.x & 63) * 64;
    const int h0 = blockIdx.y * 64;

    const uint32_t sb = smem_u32(smem);
    const int wm = wid >> 1;
    const int wn = wid & 1;

    // ---- hoisted ldsm byte offsets (relative to stage base) ----
    uint32_t aoff[2], boff[2];
    {
        int rr0 = wm * 32 + (lane & 15);
        int ka  = (lane >> 4) << 4;
        aoff[0] = (uint32_t)((rr0 +  0) * SSTR + ka);
        aoff[1] = (uint32_t)((rr0 + 16) * SSTR + ka);
        int rbase = wn * 32 + ((lane >> 4) << 3) + (lane & 7);
        int kb    = ((lane >> 3) & 1) << 4;
        boff[0] = (uint32_t)(OFF_BH + (rbase +  0) * SSTR + kb);
        boff[1] = (uint32_t)(OFF_BH + (rbase + 16) * SSTR + kb);
    }

    // ---- cp.async mapping: 6 x 16B per thread per stage ----
    const char* srcs[6];
    uint32_t    dsts[6];
    #pragma unroll
    for (int j = 0; j < 6; j++) {
        int id = tid + 256 * j;
        if (id < 1024) {
            int plane = id >> 9;
            int rem   = id & 511;
            int row   = rem >> 2;
            int seg   = rem & 3;
            int arow  = h0 + row + ((row >= 64) ? 448 : 0);
            const __nv_bfloat16* base = plane ? d_Wl : d_Wh;
            srcs[j] = (const char*)(base + (size_t)arow * H_) + seg * 16;
            dsts[j] = sb + plane * TILE_A + row * SSTR + seg * 16;
        } else {
            int idb   = id - 1024;
            int plane = idb >> 8;
            int rem   = idb & 255;
            int row   = rem >> 2;
            int seg   = rem & 3;
            const __nv_bfloat16* base =
                (plane ? d_gTl : d_gTh) + (size_t)b * L_ * H_;
            srcs[j] = (const char*)(base + (size_t)(l0 + row) * H_) + seg * 16;
            dsts[j] = sb + OFF_BH + plane * TILE_Bs + row * SSTR + seg * 16;
        }
    }

    #pragma unroll
    for (int j = 0; j < 6; j++) CP_ASYNC16(dsts[j], srcs[j]);
    CP_COMMIT();
    #pragma unroll
    for (int j = 0; j < 6; j++) CP_ASYNC16(dsts[j] + STAGEB, srcs[j] + 64);
    CP_COMMIT();

    float acc[2][4][4];
    #pragma unroll
    for (int mf = 0; mf < 2; mf++)
        #pragma unroll
        for (int nf = 0; nf < 4; nf++)
            #pragma unroll
            for (int e = 0; e < 4; e++) acc[mf][nf][e] = 0.0f;

    for (int s = 0; s < NSTAGE; s++) {
        if (s == NSTAGE - 1) { CP_WAIT0(); } else { CP_WAIT1(); }
        __syncthreads();

        const uint32_t st = sb + (uint32_t)(s % 3) * STAGEB;

        #pragma unroll
        for (int ks = 0; ks < 2; ks++) {
            const uint32_t kso = (uint32_t)(ks * 32);
            uint32_t aH[2][4], aL[2][4], bH[2][4], bL[2][4];
            #pragma unroll
            for (int mf = 0; mf < 2; mf++) {
                uint32_t addr = st + aoff[mf] + kso;
                ldsm4(aH[mf], addr);
                ldsm4(aL[mf], addr + TILE_A);
            }
            #pragma unroll
            for (int jb = 0; jb < 2; jb++) {
                uint32_t addr = st + boff[jb] + kso;
                ldsm4(bH[jb], addr);
                ldsm4(bL[jb], addr + TILE_Bs);
            }
            // pass 1: hi*hi (8 independent accumulators)
            #pragma unroll
            for (int mf = 0; mf < 2; mf++)
                #pragma unroll
                for (int jb = 0; jb < 2; jb++)
                    #pragma unroll
                    for (int hh = 0; hh < 2; hh++)
                        mma16816(acc[mf][jb * 2 + hh], aH[mf],
                                 bH[jb][2 * hh], bH[jb][2 * hh + 1]);
            // pass 2: hi*lo
            #pragma unroll
            for (int mf = 0; mf < 2; mf++)
                #pragma unroll
                for (int jb = 0; jb < 2; jb++)
                    #pragma unroll
                    for (int hh = 0; hh < 2; hh++)
                        mma16816(acc[mf][jb * 2 + hh], aH[mf],
                                 bL[jb][2 * hh], bL[jb][2 * hh + 1]);
            // pass 3: lo*hi
            #pragma unroll
            for (int mf = 0; mf < 2; mf++)
                #pragma unroll
                for (int jb = 0; jb < 2; jb++)
                    #pragma unroll
                    for (int hh = 0; hh < 2; hh++)
                        mma16816(acc[mf][jb * 2 + hh], aL[mf],
                                 bH[jb][2 * hh], bH[jb][2 * hh + 1]);
        }

        if (s + 2 < NSTAGE) {
            uint32_t dbo = (uint32_t)((s + 2) % 3) * STAGEB;
            size_t   sbo = (size_t)(s + 2) * 64;
            #pragma unroll
            for (int j = 0; j < 6; j++) CP_ASYNC16(dsts[j] + dbo, srcs[j] + sbo);
            CP_COMMIT();
        }
    }
    __syncthreads();

    // ---- epilogue: GLU ----
    float* sg = (float*)smem;               // [64][66] f32
    const int r0 = (lane >> 2);
    const int c0 = (lane & 3) * 2;

    if (wm >= 2) {
        #pragma unroll
        for (int mf = 0; mf < 2; mf++) {
            int row = wm * 32 + mf * 16 + r0;
            int grow = row - 64;
            float bg  = bias[H_ + h0 + grow];
            float bg2 = bias[H_ + h0 + grow + 8];
            #pragma unroll
            for (int nf = 0; nf < 4; nf++) {
                int col = wn * 32 + nf * 8 + c0;
                *(float2*)&sg[grow * 66 + col] =
                    make_float2(acc[mf][nf][0] + bg, acc[mf][nf][1] + bg);
                *(float2*)&sg[(grow + 8) * 66 + col] =
                    make_float2(acc[mf][nf][2] + bg2, acc[mf][nf][3] + bg2);
            }
        }
    }
    __syncthreads();
    if (wm < 2) {
        #pragma unroll
        for (int mf = 0; mf < 2; mf++) {
            int row = wm * 32 + mf * 16 + r0;
            int h  = h0 + row;
            float ba  = bias[h];
            float ba2 = bias[h + 8];
            float* ob  = out + ((size_t)b * H_ + h) * L_ + l0;
            float* ob2 = out + ((size_t)b * H_ + h + 8) * L_ + l0;
            #pragma unroll
            for (int nf = 0; nf < 4; nf++) {
                int col = wn * 32 + nf * 8 + c0;
                float2 g0 = *(const float2*)&sg[row * 66 + col];
                float2 g1 = *(const float2*)&sg[(row + 8) * 66 + col];
                float2 o0, o1;
                o0.x = (acc[mf][nf][0] + ba)  / (1.0f + expf(-g0.x));
                o0.y = (acc[mf][nf][1] + ba)  / (1.0f + expf(-g0.y));
                o1.x = (acc[mf][nf][2] + ba2) / (1.0f + expf(-g1.x));
                o1.y = (acc[mf][nf][3] + ba2) / (1.0f + expf(-g1.y));
                *(float2*)(ob  + col) = o0;
                *(float2*)(ob2 + col) = o1;
            }
        }
    }
}

// ---------------------------------------------------------------------------
extern "C" void kernel_launch(void* const* d_in, const int* in_sizes, int n_in,
                              void* d_out, int out_size)
{
    const float* u          = (const float*)d_in[0];
    const float* log_dt     = (const float*)d_in[1];
    const float* log_A_real = (const float*)d_in[2];
    const float* A_imag     = (const float*)d_in[3];
    const float* C          = (const float*)d_in[4];
    const float* D          = (const float*)d_in[5];
    const float* W_out      = (const float*)d_in[6];
    const float* b_out      = (const float*)d_in[7];
    float* out = (float*)d_out;

    static bool attr_set = false;
    if (!attr_set) {
        cudaFuncSetAttribute(gemm_glu_mma, cudaFuncAttributeMaxDynamicSharedMemorySize,
                             SMEM_BYTES);
        attr_set = true;
    }

    prep_kernel<<<(HN + 127) / 128, 128>>>(log_dt, log_A_real, A_imag, C);
    wsplit_kernel<<<(O_ * H_ + 255) / 256, 256>>>(W_out);
    scan_kernel<<<(B_ * H_) / 8, 256>>>(u, D);

    dim3 grid(B_ * (L_ / 64), H_ / 64);     // (512, 8)
    gemm_glu_mma<<<grid, 256, SMEM_BYTES>>>(b_out, out);
}

// round 7
// speedup vs baseline: 2.3089x; 1.2350x over previous
#include <cuda_runtime.h>
#include <cuda_fp16.h>
#include <math.h>
#include <stdint.h>

#define B_ 8
#define H_ 512
#define L_ 4096
#define N_ 32
#define HN (H_ * N_)
#define O_ (2 * H_)

// ---------------- scratch (__device__ globals) -----------------------------
__device__ float d_wr[HN], d_wi[HN], d_csr[HN], d_csi[HN];
__device__ __half d_gT[(size_t)B_ * L_ * H_];     // single fp16 plane
__device__ __half d_Wh[(size_t)O_ * H_];
__device__ __half d_Wl[(size_t)O_ * H_];

// ---------------------------------------------------------------------------
__device__ __forceinline__ uint32_t smem_u32(const void* p) {
    uint32_t a;
    asm("{ .reg .u64 t; cvta.to.shared.u64 t, %1; cvt.u32.u64 %0, t; }"
        : "=r"(a) : "l"(p));
    return a;
}

#define CP_ASYNC16(dst, src) \
    asm volatile("cp.async.cg.shared.global [%0], [%1], 16;" :: "r"(dst), "l"(src))
#define CP_COMMIT() asm volatile("cp.async.commit_group;" ::: "memory")
#define CP_WAIT1()  asm volatile("cp.async.wait_group 1;" ::: "memory")
#define CP_WAIT0()  asm volatile("cp.async.wait_group 0;" ::: "memory")

__device__ __forceinline__ void ldsm4(uint32_t* r, uint32_t addr) {
    asm volatile("ldmatrix.sync.aligned.m8n8.x4.shared.b16 {%0,%1,%2,%3}, [%4];"
                 : "=r"(r[0]), "=r"(r[1]), "=r"(r[2]), "=r"(r[3]) : "r"(addr));
}

__device__ __forceinline__ void mma16816(float* d, const uint32_t* a,
                                         uint32_t b0, uint32_t b1) {
    asm volatile("mma.sync.aligned.m16n8k16.row.col.f32.f16.f16.f32 "
                 "{%0,%1,%2,%3}, {%4,%5,%6,%7}, {%8,%9}, {%0,%1,%2,%3};"
                 : "+f"(d[0]), "+f"(d[1]), "+f"(d[2]), "+f"(d[3])
                 : "r"(a[0]), "r"(a[1]), "r"(a[2]), "r"(a[3]), "r"(b0), "r"(b1));
}

// ---------------------------------------------------------------------------
// Kernel 1: per (h,n) precompute  w = exp(dt*A),  2*Cs = 2*C*(w-1)/A
// ---------------------------------------------------------------------------
__global__ void prep_kernel(const float* __restrict__ log_dt,
                            const float* __restrict__ log_A_real,
                            const float* __restrict__ A_imag,
                            const float* __restrict__ C)
{
    int idx = blockIdx.x * blockDim.x + threadIdx.x;
    if (idx >= HN) return;
    int h = idx / N_;
    float dt = expf(log_dt[h]);
    float ar = -expf(log_A_real[idx]);
    float ai = A_imag[idx];
    float mag = expf(dt * ar);
    float wr = mag * cosf(dt * ai);
    float wi = mag * sinf(dt * ai);
    float den = ar * ar + ai * ai;
    float nr = wr - 1.0f, ni = wi;
    float qr = (nr * ar + ni * ai) / den;
    float qi = (ni * ar - nr * ai) / den;
    float Cr = C[2 * idx], Ci = C[2 * idx + 1];
    d_wr[idx]  = wr;
    d_wi[idx]  = wi;
    d_csr[idx] = 2.0f * (Cr * qr - Ci * qi);
    d_csi[idx] = 2.0f * (Cr * qi + Ci * qr);
}

// ---------------------------------------------------------------------------
// Kernel 1b: split W into fp16 hi/lo
// ---------------------------------------------------------------------------
__global__ void wsplit_kernel(const float* __restrict__ W)
{
    int idx = blockIdx.x * blockDim.x + threadIdx.x;
    if (idx >= O_ * H_) return;
    float w = W[idx];
    __half hi = __float2half(w);
    __half lo = __float2half(w - __half2float(hi));
    d_Wh[idx] = hi;
    d_Wl[idx] = lo;
}

// ---------------------------------------------------------------------------
// Kernel 2: scan. 8 warps/block = 8 consecutive h of one b.
// Per step: 1 shfl broadcast + 5 FMA-class + 1 STS (deferred reduction).
// u prefetched one group ahead (LDG hidden behind full group of work).
// Per group: float2 column sums, GELU, smem transpose, 16B-contiguous fp16
// stores, one barrier (double-buffered tr).
// ---------------------------------------------------------------------------
__global__ __launch_bounds__(256) void scan_kernel(const float* __restrict__ u,
                                                   const float* __restrict__ D)
{
    __shared__ float    red[8][32][34];   // rows 8B-aligned, float2-readable
    __shared__ uint16_t tr[2][8][36];     // double-buffered transpose staging

    const int tid  = threadIdx.x;
    const int wid  = tid >> 5;
    const int lane = tid & 31;

    const int gw     = blockIdx.x * 8 + wid;
    const int b      = gw >> 9;
    const int h      = gw & 511;
    const int h_base = (blockIdx.x * 8) & 511;

    const int idx = h * N_ + lane;
    const float wr = d_wr[idx], wi = d_wi[idx];
    const float cr = d_csr[idx], nci = -d_csi[idx];
    const float Dh = D[h];

    const float* up = u + ((size_t)b * H_ + h) * L_;
    const size_t obase = (size_t)b * L_ * H_ + h_base;

    const int sl = tid >> 3;        // l within group (0..31)
    const int sh = tid & 7;         // h column (0..7)

    float xr = 0.0f, xi = 0.0f;
    float uv_next = up[lane];       // prefetch group 0

    for (int l0 = 0; l0 < L_; l0 += 32) {
        const int p = (l0 >> 5) & 1;
        float uv = uv_next;
        if (l0 + 32 < L_) uv_next = up[l0 + 32 + lane];   // prefetch next group
        #pragma unroll
        for (int t = 0; t < 32; t++) {
            float ut = __shfl_sync(0xffffffffu, uv, t);
            float t0  = fmaf(-wi, xi, ut);
            float t1  = wi * xr;
            float nxr = fmaf(wr, xr, t0);
            float nxi = fmaf(wr, xi, t1);
            xr = nxr; xi = nxi;
            red[wid][t][lane] = fmaf(cr, xr, nci * xi);
        }
        __syncwarp();
        // lane t sums the 32 mode-contributions for timestep t (float2 loads)
        const float2* rp = (const float2*)red[wid][lane];
        float s0 = 0.0f, s1 = 0.0f, s2 = 0.0f, s3 = 0.0f;
        #pragma unroll
        for (int j = 0; j < 8; j++) {
            float2 a = rp[2 * j], c2 = rp[2 * j + 1];
            s0 += a.x; s1 += a.y; s2 += c2.x; s3 += c2.y;
        }
        float y = fmaf(Dh, uv, (s0 + s1) + (s2 + s3));   // uv = u at t=lane
        float gv = 0.5f * y * (1.0f + erff(y * 0.70710678118654752f));
        tr[p][wid][lane] = __half_as_ushort(__float2half(gv));
        __syncthreads();
        {
            size_t o = obase + (size_t)(l0 + sl) * H_ + sh;
            d_gT[o] = __ushort_as_half(tr[p][sh][sl]);
        }
    }
}

// ---------------------------------------------------------------------------
// Kernel 3: mma.sync fp16 GEMM + GLU (2 passes: Wh*g + Wl*g, fp32 accum).
// CTA: M=128 (rows 0-63 = a-channels h0.., rows 64-127 = gate channels
// 512+h0..), N=64 l-cols, BK=32, 3-stage cp.async pipeline.
// 8 warps (4M x 2N), warp tile 32x32, 2 CTAs/SM.
// ---------------------------------------------------------------------------
#define BK 32
#define SSTR 80
#define TILE_A 10240                        // 128 * 80
#define TILE_Bs 5120                        // 64 * 80
#define OFF_B  (2 * TILE_A)
#define STAGEB (2 * TILE_A + TILE_Bs)       // 25600
#define NSTAGE (H_ / BK)                    // 16
#define SMEM_BYTES (3 * STAGEB)             // 76800

__global__ __launch_bounds__(256, 2) void gemm_glu_mma(const float* __restrict__ bias,
                                                       float* __restrict__ out)
{
    extern __shared__ char smem[];
    const int tid  = threadIdx.x;
    const int wid  = tid >> 5;
    const int lane = tid & 31;

    const int b  = blockIdx.x >> 6;
    const int l0 = (blockIdx.x & 63) * 64;
    const int h0 = blockIdx.y * 64;

    const uint32_t sb = smem_u32(smem);
    const int wm = wid >> 1;
    const int wn = wid & 1;

    // ---- hoisted ldsm byte offsets (relative to stage base) ----
    uint32_t aoff[2], boff[2];
    {
        int rr0 = wm * 32 + (lane & 15);
        int ka  = (lane >> 4) << 4;
        aoff[0] = (uint32_t)((rr0 +  0) * SSTR + ka);
        aoff[1] = (uint32_t)((rr0 + 16) * SSTR + ka);
        int rbase = wn * 32 + ((lane >> 4) << 3) + (lane & 7);
        int kb    = ((lane >> 3) & 1) << 4;
        boff[0] = (uint32_t)(OFF_B + (rbase +  0) * SSTR + kb);
        boff[1] = (uint32_t)(OFF_B + (rbase + 16) * SSTR + kb);
    }

    // ---- cp.async mapping: 5 x 16B per thread per stage (1280 txns) ----
    const char* srcs[5];
    uint32_t    dsts[5];
    #pragma unroll
    for (int j = 0; j < 5; j++) {
        int id = tid + 256 * j;
        if (id < 1024) {
            int plane = id >> 9;              // 0=Wh 1=Wl
            int rem   = id & 511;
            int row   = rem >> 2;             // 0..127
            int seg   = rem & 3;
            int arow  = h0 + row + ((row >= 64) ? 448 : 0);
            const __half* base = plane ? d_Wl : d_Wh;
            srcs[j] = (const char*)(base + (size_t)arow * H_) + seg * 16;
            dsts[j] = sb + plane * TILE_A + row * SSTR + seg * 16;
        } else {
            int idb = id - 1024;              // 0..255
            int row = idb >> 2;               // 0..63
            int seg = idb & 3;
            const __half* base = d_gT + (size_t)b * L_ * H_;
            srcs[j] = (const char*)(base + (size_t)(l0 + row) * H_) + seg * 16;
            dsts[j] = sb + OFF_B + row * SSTR + seg * 16;
        }
    }

    #pragma unroll
    for (int j = 0; j < 5; j++) CP_ASYNC16(dsts[j], srcs[j]);
    CP_COMMIT();
    #pragma unroll
    for (int j = 0; j < 5; j++) CP_ASYNC16(dsts[j] + STAGEB, srcs[j] + 64);
    CP_COMMIT();

    float acc[2][4][4];
    #pragma unroll
    for (int mf = 0; mf < 2; mf++)
        #pragma unroll
        for (int nf = 0; nf < 4; nf++)
            #pragma unroll
            for (int e = 0; e < 4; e++) acc[mf][nf][e] = 0.0f;

    for (int s = 0; s < NSTAGE; s++) {
        if (s == NSTAGE - 1) { CP_WAIT0(); } else { CP_WAIT1(); }
        __syncthreads();

        const uint32_t st = sb + (uint32_t)(s % 3) * STAGEB;

        #pragma unroll
        for (int ks = 0; ks < 2; ks++) {
            const uint32_t kso = (uint32_t)(ks * 32);
            uint32_t aH[2][4], aL[2][4], bF[2][4];
            #pragma unroll
            for (int mf = 0; mf < 2; mf++) {
                uint32_t addr = st + aoff[mf] + kso;
                ldsm4(aH[mf], addr);
                ldsm4(aL[mf], addr + TILE_A);
            }
            #pragma unroll
            for (int jb = 0; jb < 2; jb++)
                ldsm4(bF[jb], st + boff[jb] + kso);
            // pass 1: Wh * g  (8 independent accumulators)
            #pragma unroll
            for (int mf = 0; mf < 2; mf++)
                #pragma unroll
                for (int jb = 0; jb < 2; jb++)
                    #pragma unroll
                    for (int hh = 0; hh < 2; hh++)
                        mma16816(acc[mf][jb * 2 + hh], aH[mf],
                                 bF[jb][2 * hh], bF[jb][2 * hh + 1]);
            // pass 2: Wl * g
            #pragma unroll
            for (int mf = 0; mf < 2; mf++)
                #pragma unroll
                for (int jb = 0; jb < 2; jb++)
                    #pragma unroll
                    for (int hh = 0; hh < 2; hh++)
                        mma16816(acc[mf][jb * 2 + hh], aL[mf],
                                 bF[jb][2 * hh], bF[jb][2 * hh + 1]);
        }

        if (s + 2 < NSTAGE) {
            uint32_t dbo = (uint32_t)((s + 2) % 3) * STAGEB;
            size_t   sbo = (size_t)(s + 2) * 64;
            #pragma unroll
            for (int j = 0; j < 5; j++) CP_ASYNC16(dsts[j] + dbo, srcs[j] + sbo);
            CP_COMMIT();
        }
    }
    __syncthreads();

    // ---- epilogue: GLU ----
    float* sg = (float*)smem;               // [64][66] f32
    const int r0 = (lane >> 2);
    const int c0 = (lane & 3) * 2;

    if (wm >= 2) {
        #pragma unroll
        for (int mf = 0; mf < 2; mf++) {
            int row = wm * 32 + mf * 16 + r0;
            int grow = row - 64;
            float bg  = bias[H_ + h0 + grow];
            float bg2 = bias[H_ + h0 + grow + 8];
            #pragma unroll
            for (int nf = 0; nf < 4; nf++) {
                int col = wn * 32 + nf * 8 + c0;
                *(float2*)&sg[grow * 66 + col] =
                    make_float2(acc[mf][nf][0] + bg, acc[mf][nf][1] + bg);
                *(float2*)&sg[(grow + 8) * 66 + col] =
                    make_float2(acc[mf][nf][2] + bg2, acc[mf][nf][3] + bg2);
            }
        }
    }
    __syncthreads();
    if (wm < 2) {
        #pragma unroll
        for (int mf = 0; mf < 2; mf++) {
            int row = wm * 32 + mf * 16 + r0;
            int h  = h0 + row;
            float ba  = bias[h];
            float ba2 = bias[h + 8];
            float* ob  = out + ((size_t)b * H_ + h) * L_ + l0;
            float* ob2 = out + ((size_t)b * H_ + h + 8) * L_ + l0;
            #pragma unroll
            for (int nf = 0; nf < 4; nf++) {
                int col = wn * 32 + nf * 8 + c0;
                float2 g0 = *(const float2*)&sg[row * 66 + col];
                float2 g1 = *(const float2*)&sg[(row + 8) * 66 + col];
                float2 o0, o1;
                o0.x = (acc[mf][nf][0] + ba)  / (1.0f + expf(-g0.x));
                o0.y = (acc[mf][nf][1] + ba)  / (1.0f + expf(-g0.y));
                o1.x = (acc[mf][nf][2] + ba2) / (1.0f + expf(-g1.x));
                o1.y = (acc[mf][nf][3] + ba2) / (1.0f + expf(-g1.y));
                *(float2*)(ob  + col) = o0;
                *(float2*)(ob2 + col) = o1;
            }
        }
    }
}

// ---------------------------------------------------------------------------
extern "C" void kernel_launch(void* const* d_in, const int* in_sizes, int n_in,
                              void* d_out, int out_size)
{
    const float* u          = (const float*)d_in[0];
    const float* log_dt     = (const float*)d_in[1];
    const float* log_A_real = (const float*)d_in[2];
    const float* A_imag     = (const float*)d_in[3];
    const float* C          = (const float*)d_in[4];
    const float* D          = (const float*)d_in[5];
    const float* W_out      = (const float*)d_in[6];
    const float* b_out      = (const float*)d_in[7];
    float* out = (float*)d_out;

    static bool attr_set = false;
    if (!attr_set) {
        cudaFuncSetAttribute(gemm_glu_mma, cudaFuncAttributeMaxDynamicSharedMemorySize,
                             SMEM_BYTES);
        attr_set = true;
    }

    prep_kernel<<<(HN + 127) / 128, 128>>>(log_dt, log_A_real, A_imag, C);
    wsplit_kernel<<<(O_ * H_ + 255) / 256, 256>>>(W_out);
    scan_kernel<<<(B_ * H_) / 8, 256>>>(u, D);

    dim3 grid(B_ * (L_ / 64), H_ / 64);     // (512, 8)
    gemm_glu_mma<<<grid, 256, SMEM_BYTES>>>(b_out, out);
}

// round 8
// speedup vs baseline: 2.3676x; 1.0254x over previous
#include <cuda_runtime.h>
#include <cuda_fp16.h>
#include <math.h>
#include <stdint.h>

#define B_ 8
#define H_ 512
#define L_ 4096
#define N_ 32
#define HN (H_ * N_)
#define O_ (2 * H_)

// ---------------- scratch (__device__ globals) -----------------------------
__device__ float d_wr[HN], d_wi[HN], d_csr[HN], d_csi[HN];
__device__ __half d_g[(size_t)B_ * H_ * L_];      // natural layout [b][h][l]
__device__ __half d_Wh[(size_t)O_ * H_];
__device__ __half d_Wl[(size_t)O_ * H_];

// ---------------------------------------------------------------------------
__device__ __forceinline__ uint32_t smem_u32(const void* p) {
    uint32_t a;
    asm("{ .reg .u64 t; cvta.to.shared.u64 t, %1; cvt.u32.u64 %0, t; }"
        : "=r"(a) : "l"(p));
    return a;
}

#define CP_ASYNC16(dst, src) \
    asm volatile("cp.async.cg.shared.global [%0], [%1], 16;" :: "r"(dst), "l"(src))
#define CP_COMMIT() asm volatile("cp.async.commit_group;" ::: "memory")
#define CP_WAIT1()  asm volatile("cp.async.wait_group 1;" ::: "memory")
#define CP_WAIT0()  asm volatile("cp.async.wait_group 0;" ::: "memory")

__device__ __forceinline__ void ldsm4(uint32_t* r, uint32_t addr) {
    asm volatile("ldmatrix.sync.aligned.m8n8.x4.shared.b16 {%0,%1,%2,%3}, [%4];"
                 : "=r"(r[0]), "=r"(r[1]), "=r"(r[2]), "=r"(r[3]) : "r"(addr));
}
__device__ __forceinline__ void ldsm4t(uint32_t* r, uint32_t addr) {
    asm volatile("ldmatrix.sync.aligned.m8n8.x4.trans.shared.b16 {%0,%1,%2,%3}, [%4];"
                 : "=r"(r[0]), "=r"(r[1]), "=r"(r[2]), "=r"(r[3]) : "r"(addr));
}

__device__ __forceinline__ void mma16816(float* d, const uint32_t* a,
                                         uint32_t b0, uint32_t b1) {
    asm volatile("mma.sync.aligned.m16n8k16.row.col.f32.f16.f16.f32 "
                 "{%0,%1,%2,%3}, {%4,%5,%6,%7}, {%8,%9}, {%0,%1,%2,%3};"
                 : "+f"(d[0]), "+f"(d[1]), "+f"(d[2]), "+f"(d[3])
                 : "r"(a[0]), "r"(a[1]), "r"(a[2]), "r"(a[3]), "r"(b0), "r"(b1));
}

// ---------------------------------------------------------------------------
// Kernel 1: per (h,n) precompute  w = exp(dt*A),  2*Cs = 2*C*(w-1)/A
// ---------------------------------------------------------------------------
__global__ void prep_kernel(const float* __restrict__ log_dt,
                            const float* __restrict__ log_A_real,
                            const float* __restrict__ A_imag,
                            const float* __restrict__ C)
{
    int idx = blockIdx.x * blockDim.x + threadIdx.x;
    if (idx >= HN) return;
    int h = idx / N_;
    float dt = expf(log_dt[h]);
    float ar = -expf(log_A_real[idx]);
    float ai = A_imag[idx];
    float mag = expf(dt * ar);
    float wr = mag * cosf(dt * ai);
    float wi = mag * sinf(dt * ai);
    float den = ar * ar + ai * ai;
    float nr = wr - 1.0f, ni = wi;
    float qr = (nr * ar + ni * ai) / den;
    float qi = (ni * ar - nr * ai) / den;
    float Cr = C[2 * idx], Ci = C[2 * idx + 1];
    d_wr[idx]  = wr;
    d_wi[idx]  = wi;
    d_csr[idx] = 2.0f * (Cr * qr - Ci * qi);
    d_csi[idx] = 2.0f * (Cr * qi + Ci * qr);
}

// ---------------------------------------------------------------------------
// Kernel 1b: split W into fp16 hi/lo
// ---------------------------------------------------------------------------
__global__ void wsplit_kernel(const float* __restrict__ W)
{
    int idx = blockIdx.x * blockDim.x + threadIdx.x;
    if (idx >= O_ * H_) return;
    float w = W[idx];
    __half hi = __float2half(w);
    __half lo = __float2half(w - __half2float(hi));
    d_Wh[idx] = hi;
    d_Wl[idx] = lo;
}

// ---------------------------------------------------------------------------
// Kernel 2: scan. Pure warp-local: one warp per (b,h), no block barriers.
// Per step: 1 shfl broadcast + 5 FMA + 1 STS (deferred reduction).
// Per group: float2 column sums, GELU, 64B-coalesced fp16 store to d_g[b][h][l].
// u prefetched one group ahead.
// ---------------------------------------------------------------------------
__global__ __launch_bounds__(256) void scan_kernel(const float* __restrict__ u,
                                                   const float* __restrict__ D)
{
    __shared__ float red[8][32][34];   // [warp][t][lane], rows 8B-aligned

    const int tid  = threadIdx.x;
    const int wid  = tid >> 5;
    const int lane = tid & 31;

    const int gw = blockIdx.x * 8 + wid;
    const int b  = gw >> 9;
    const int h  = gw & 511;

    const int idx = h * N_ + lane;
    const float wr = d_wr[idx], wi = d_wi[idx];
    const float cr = d_csr[idx], nci = -d_csi[idx];
    const float Dh = D[h];

    const float* up = u   + ((size_t)b * H_ + h) * L_;
    __half*      gp = d_g + ((size_t)b * H_ + h) * L_;

    float xr = 0.0f, xi = 0.0f;
    float uv_next = up[lane];       // prefetch group 0

    for (int l0 = 0; l0 < L_; l0 += 32) {
        float uv = uv_next;
        if (l0 + 32 < L_) uv_next = up[l0 + 32 + lane];
        #pragma unroll
        for (int t = 0; t < 32; t++) {
            float ut = __shfl_sync(0xffffffffu, uv, t);
            float t0  = fmaf(-wi, xi, ut);
            float t1  = wi * xr;
            float nxr = fmaf(wr, xr, t0);
            float nxi = fmaf(wr, xi, t1);
            xr = nxr; xi = nxi;
            red[wid][t][lane] = fmaf(cr, xr, nci * xi);
        }
        __syncwarp();
        const float2* rp = (const float2*)red[wid][lane];
        float s0 = 0.0f, s1 = 0.0f, s2 = 0.0f, s3 = 0.0f;
        #pragma unroll
        for (int j = 0; j < 8; j++) {
            float2 a = rp[2 * j], c2 = rp[2 * j + 1];
            s0 += a.x; s1 += a.y; s2 += c2.x; s3 += c2.y;
        }
        float y = fmaf(Dh, uv, (s0 + s1) + (s2 + s3));   // uv = u at t=lane
        float gv = 0.5f * y * (1.0f + erff(y * 0.70710678118654752f));
        gp[l0 + lane] = __float2half(gv);
        __syncwarp();
    }
}

// ---------------------------------------------------------------------------
// Kernel 3: mma.sync fp16 GEMM + GLU (2 passes: Wh*g + Wl*g, fp32 accum).
// CTA: M=128 (rows 0-63 = a-channels h0.., rows 64-127 = gate channels
// 512+h0..), N=64 l-cols, BK=32, 3-stage cp.async pipeline.
// B loaded from natural-layout g[b][h][l] as [k=h rows][n=l cols] tiles,
// consumed via ldmatrix.x4.trans. 8 warps (4M x 2N), 2 CTAs/SM.
// ---------------------------------------------------------------------------
#define BK 32
#define SSTR 80                              // A rows: 64B data + 16B pad
#define SSTRB 144                            // B rows: 128B data + 16B pad
#define TILE_A 10240                         // 128 * 80
#define TILE_B (BK * SSTRB)                  // 4608
#define OFF_B  (2 * TILE_A)
#define STAGEB (2 * TILE_A + TILE_B)         // 25088
#define NSTAGE (H_ / BK)                     // 16
#define SMEM_BYTES (3 * STAGEB)              // 75264
#define BSRC_STRIDE ((size_t)BK * L_ * 2)    // 262144 bytes per stage

__global__ __launch_bounds__(256, 2) void gemm_glu_mma(const float* __restrict__ bias,
                                                       float* __restrict__ out)
{
    extern __shared__ char smem[];
    const int tid  = threadIdx.x;
    const int wid  = tid >> 5;
    const int lane = tid & 31;

    const int b  = blockIdx.x >> 6;
    const int l0 = (blockIdx.x & 63) * 64;
    const int h0 = blockIdx.y * 64;

    const uint32_t sb = smem_u32(smem);
    const int wm = wid >> 1;
    const int wn = wid & 1;

    // ---- hoisted ldsm byte offsets (relative to stage base) ----
    uint32_t aoff[2], boff[2];
    {
        int rr0 = wm * 32 + (lane & 15);
        int ka  = (lane >> 4) << 4;                      // bytes
        aoff[0] = (uint32_t)((rr0 +  0) * SSTR + ka);
        aoff[1] = (uint32_t)((rr0 + 16) * SSTR + ka);
        // B (trans): lane -> &B[(lane&15)][n0 + ((lane>>4)<<3)]
        int nb = (wn * 32 + ((lane >> 4) << 3)) * 2;     // bytes
        boff[0] = (uint32_t)(OFF_B + (lane & 15) * SSTRB + nb);
        boff[1] = boff[0] + 32;                          // +16 cols * 2B
    }

    // ---- cp.async mapping: 5 x 16B per thread per stage ----
    // j0..j3: A planes (Wh,Wl), per-stage src stride 64B
    // j4    : B (g), per-stage src stride BK*L*2
    const char* srcs[5];
    uint32_t    dsts[5];
    #pragma unroll
    for (int j = 0; j < 4; j++) {
        int id    = tid + 256 * j;
        int plane = id >> 9;                  // 0=Wh 1=Wl
        int rem   = id & 511;
        int row   = rem >> 2;                 // 0..127
        int seg   = rem & 3;
        int arow  = h0 + row + ((row >= 64) ? 448 : 0);
        const __half* base = plane ? d_Wl : d_Wh;
        srcs[j] = (const char*)(base + (size_t)arow * H_) + seg * 16;
        dsts[j] = sb + plane * TILE_A + row * SSTR + seg * 16;
    }
    {
        int idb = tid;                        // 0..255
        int row = idb >> 3;                   // 0..31 (k rows)
        int seg = idb & 7;                    // 8 x 16B = 128B row
        const __half* base = d_g + (size_t)b * H_ * L_;
        srcs[4] = (const char*)(base + (size_t)row * L_ + l0) + seg * 16;
        dsts[4] = sb + OFF_B + row * SSTRB + seg * 16;
    }

    // prologue: stages 0 and 1
    #pragma unroll
    for (int j = 0; j < 4; j++) CP_ASYNC16(dsts[j], srcs[j]);
    CP_ASYNC16(dsts[4], srcs[4]);
    CP_COMMIT();
    #pragma unroll
    for (int j = 0; j < 4; j++) CP_ASYNC16(dsts[j] + STAGEB, srcs[j] + 64);
    CP_ASYNC16(dsts[4] + STAGEB, srcs[4] + BSRC_STRIDE);
    CP_COMMIT();

    float acc[2][4][4];
    #pragma unroll
    for (int mf = 0; mf < 2; mf++)
        #pragma unroll
        for (int nf = 0; nf < 4; nf++)
            #pragma unroll
            for (int e = 0; e < 4; e++) acc[mf][nf][e] = 0.0f;

    for (int s = 0; s < NSTAGE; s++) {
        if (s == NSTAGE - 1) { CP_WAIT0(); } else { CP_WAIT1(); }
        __syncthreads();

        const uint32_t st = sb + (uint32_t)(s % 3) * STAGEB;

        #pragma unroll
        for (int ks = 0; ks < 2; ks++) {
            const uint32_t ksoA = (uint32_t)(ks * 32);           // 16 fp16
            const uint32_t ksoB = (uint32_t)(ks * 16 * SSTRB);   // 16 k-rows
            uint32_t aH[2][4], aL[2][4], bF[2][4];
            #pragma unroll
            for (int mf = 0; mf < 2; mf++) {
                uint32_t addr = st + aoff[mf] + ksoA;
                ldsm4(aH[mf], addr);
                ldsm4(aL[mf], addr + TILE_A);
            }
            #pragma unroll
            for (int jb = 0; jb < 2; jb++)
                ldsm4t(bF[jb], st + boff[jb] + ksoB);
            // pass 1: Wh * g  (8 independent accumulators)
            #pragma unroll
            for (int mf = 0; mf < 2; mf++)
                #pragma unroll
                for (int jb = 0; jb < 2; jb++)
                    #pragma unroll
                    for (int hh = 0; hh < 2; hh++)
                        mma16816(acc[mf][jb * 2 + hh], aH[mf],
                                 bF[jb][2 * hh], bF[jb][2 * hh + 1]);
            // pass 2: Wl * g
            #pragma unroll
            for (int mf = 0; mf < 2; mf++)
                #pragma unroll
                for (int jb = 0; jb < 2; jb++)
                    #pragma unroll
                    for (int hh = 0; hh < 2; hh++)
                        mma16816(acc[mf][jb * 2 + hh], aL[mf],
                                 bF[jb][2 * hh], bF[jb][2 * hh + 1]);
        }

        if (s + 2 < NSTAGE) {
            uint32_t dbo = (uint32_t)((s + 2) % 3) * STAGEB;
            #pragma unroll
            for (int j = 0; j < 4; j++)
                CP_ASYNC16(dsts[j] + dbo, srcs[j] + (size_t)(s + 2) * 64);
            CP_ASYNC16(dsts[4] + dbo, srcs[4] + (size_t)(s + 2) * BSRC_STRIDE);
            CP_COMMIT();
        }
    }
    __syncthreads();

    // ---- epilogue: GLU ----
    float* sg = (float*)smem;               // [64][66] f32
    const int r0 = (lane >> 2);
    const int c0 = (lane & 3) * 2;

    if (wm >= 2) {
        #pragma unroll
        for (int mf = 0; mf < 2; mf++) {
            int row = wm * 32 + mf * 16 + r0;
            int grow = row - 64;
            float bg  = bias[H_ + h0 + grow];
            float bg2 = bias[H_ + h0 + grow + 8];
            #pragma unroll
            for (int nf = 0; nf < 4; nf++) {
                int col = wn * 32 + nf * 8 + c0;
                *(float2*)&sg[grow * 66 + col] =
                    make_float2(acc[mf][nf][0] + bg, acc[mf][nf][1] + bg);
                *(float2*)&sg[(grow + 8) * 66 + col] =
                    make_float2(acc[mf][nf][2] + bg2, acc[mf][nf][3] + bg2);
            }
        }
    }
    __syncthreads();
    if (wm < 2) {
        #pragma unroll
        for (int mf = 0; mf < 2; mf++) {
            int row = wm * 32 + mf * 16 + r0;
            int h  = h0 + row;
            float ba  = bias[h];
            float ba2 = bias[h + 8];
            float* ob  = out + ((size_t)b * H_ + h) * L_ + l0;
            float* ob2 = out + ((size_t)b * H_ + h + 8) * L_ + l0;
            #pragma unroll
            for (int nf = 0; nf < 4; nf++) {
                int col = wn * 32 + nf * 8 + c0;
                float2 g0 = *(const float2*)&sg[row * 66 + col];
                float2 g1 = *(const float2*)&sg[(row + 8) * 66 + col];
                float2 o0, o1;
                o0.x = (acc[mf][nf][0] + ba)  / (1.0f + expf(-g0.x));
                o0.y = (acc[mf][nf][1] + ba)  / (1.0f + expf(-g0.y));
                o1.x = (acc[mf][nf][2] + ba2) / (1.0f + expf(-g1.x));
                o1.y = (acc[mf][nf][3] + ba2) / (1.0f + expf(-g1.y));
                *(float2*)(ob  + col) = o0;
                *(float2*)(ob2 + col) = o1;
            }
        }
    }
}

// ---------------------------------------------------------------------------
extern "C" void kernel_launch(void* const* d_in, const int* in_sizes, int n_in,
                              void* d_out, int out_size)
{
    const float* u          = (const float*)d_in[0];
    const float* log_dt     = (const float*)d_in[1];
    const float* log_A_real = (const float*)d_in[2];
    const float* A_imag     = (const float*)d_in[3];
    const float* C          = (const float*)d_in[4];
    const float* D          = (const float*)d_in[5];
    const float* W_out      = (const float*)d_in[6];
    const float* b_out      = (const float*)d_in[7];
    float* out = (float*)d_out;

    static bool attr_set = false;
    if (!attr_set) {
        cudaFuncSetAttribute(gemm_glu_mma, cudaFuncAttributeMaxDynamicSharedMemorySize,
                             SMEM_BYTES);
        attr_set = true;
    }

    prep_kernel<<<(HN + 127) / 128, 128>>>(log_dt, log_A_real, A_imag, C);
    wsplit_kernel<<<(O_ * H_ + 255) / 256, 256>>>(W_out);
    scan_kernel<<<(B_ * H_) / 8, 256>>>(u, D);

    dim3 grid(B_ * (L_ / 64), H_ / 64);     // (512, 8)
    gemm_glu_mma<<<grid, 256, SMEM_BYTES>>>(b_out, out);
}

// round 9
// speedup vs baseline: 3.1881x; 1.3466x over previous
#include <cuda_runtime.h>
#include <cuda_fp16.h>
#include <math.h>
#include <stdint.h>

#define B_ 8
#define H_ 512
#define L_ 4096
#define N_ 32
#define HN (H_ * N_)
#define O_ (2 * H_)

// ---------------- scratch (__device__ globals) -----------------------------
__device__ float d_wr[HN], d_wi[HN], d_csr[HN], d_csi[HN];
__device__ __half d_g[(size_t)B_ * H_ * L_];      // natural layout [b][h][l]
__device__ __half d_Wf[(size_t)O_ * H_];          // single fp16 W plane

// ---------------------------------------------------------------------------
__device__ __forceinline__ uint32_t smem_u32(const void* p) {
    uint32_t a;
    asm("{ .reg .u64 t; cvta.to.shared.u64 t, %1; cvt.u32.u64 %0, t; }"
        : "=r"(a) : "l"(p));
    return a;
}

#define CP_ASYNC16(dst, src) \
    asm volatile("cp.async.cg.shared.global [%0], [%1], 16;" :: "r"(dst), "l"(src))
#define CP_COMMIT() asm volatile("cp.async.commit_group;" ::: "memory")
#define CP_WAIT1()  asm volatile("cp.async.wait_group 1;" ::: "memory")
#define CP_WAIT0()  asm volatile("cp.async.wait_group 0;" ::: "memory")

__device__ __forceinline__ void ldsm4(uint32_t* r, uint32_t addr) {
    asm volatile("ldmatrix.sync.aligned.m8n8.x4.shared.b16 {%0,%1,%2,%3}, [%4];"
                 : "=r"(r[0]), "=r"(r[1]), "=r"(r[2]), "=r"(r[3]) : "r"(addr));
}
__device__ __forceinline__ void ldsm4t(uint32_t* r, uint32_t addr) {
    asm volatile("ldmatrix.sync.aligned.m8n8.x4.trans.shared.b16 {%0,%1,%2,%3}, [%4];"
                 : "=r"(r[0]), "=r"(r[1]), "=r"(r[2]), "=r"(r[3]) : "r"(addr));
}

__device__ __forceinline__ void mma16816(float* d, const uint32_t* a,
                                         uint32_t b0, uint32_t b1) {
    asm volatile("mma.sync.aligned.m16n8k16.row.col.f32.f16.f16.f32 "
                 "{%0,%1,%2,%3}, {%4,%5,%6,%7}, {%8,%9}, {%0,%1,%2,%3};"
                 : "+f"(d[0]), "+f"(d[1]), "+f"(d[2]), "+f"(d[3])
                 : "r"(a[0]), "r"(a[1]), "r"(a[2]), "r"(a[3]), "r"(b0), "r"(b1));
}

// ---------------------------------------------------------------------------
// Kernel 1: per (h,n) precompute  w = exp(dt*A),  2*Cs = 2*C*(w-1)/A
// ---------------------------------------------------------------------------
__global__ void prep_kernel(const float* __restrict__ log_dt,
                            const float* __restrict__ log_A_real,
                            const float* __restrict__ A_imag,
                            const float* __restrict__ C)
{
    int idx = blockIdx.x * blockDim.x + threadIdx.x;
    if (idx >= HN) return;
    int h = idx / N_;
    float dt = expf(log_dt[h]);
    float ar = -expf(log_A_real[idx]);
    float ai = A_imag[idx];
    float mag = expf(dt * ar);
    float wr = mag * cosf(dt * ai);
    float wi = mag * sinf(dt * ai);
    float den = ar * ar + ai * ai;
    float nr = wr - 1.0f, ni = wi;
    float qr = (nr * ar + ni * ai) / den;
    float qi = (ni * ar - nr * ai) / den;
    float Cr = C[2 * idx], Ci = C[2 * idx + 1];
    d_wr[idx]  = wr;
    d_wi[idx]  = wi;
    d_csr[idx] = 2.0f * (Cr * qr - Ci * qi);
    d_csi[idx] = 2.0f * (Cr * qi + Ci * qr);
}

// ---------------------------------------------------------------------------
// Kernel 1b: convert W to fp16
// ---------------------------------------------------------------------------
__global__ void wconv_kernel(const float* __restrict__ W)
{
    int idx = blockIdx.x * blockDim.x + threadIdx.x;
    if (idx >= O_ * H_) return;
    d_Wf[idx] = __float2half(W[idx]);
}

// ---------------------------------------------------------------------------
// Kernel 2: scan. Pure warp-local: one warp per (b,h).
// Per step: 1 shfl + 5 FMA + 1 STS (deferred reduction).
// u prefetched TWO groups ahead (~700 cyc, covers DRAM latency).
// Per group: float2 column sums, GELU, 64B-coalesced fp16 store.
// ---------------------------------------------------------------------------
__global__ __launch_bounds__(256) void scan_kernel(const float* __restrict__ u,
                                                   const float* __restrict__ D)
{
    __shared__ float red[8][32][34];   // [warp][t][lane], rows 8B-aligned

    const int tid  = threadIdx.x;
    const int wid  = tid >> 5;
    const int lane = tid & 31;

    const int gw = blockIdx.x * 8 + wid;
    const int b  = gw >> 9;
    const int h  = gw & 511;

    const int idx = h * N_ + lane;
    const float wr = d_wr[idx], wi = d_wi[idx];
    const float cr = d_csr[idx], nci = -d_csi[idx];
    const float Dh = D[h];

    const float* up = u   + ((size_t)b * H_ + h) * L_;
    __half*      gp = d_g + ((size_t)b * H_ + h) * L_;

    float xr = 0.0f, xi = 0.0f;
    float uv_next  = up[lane];          // group 0
    float uv_next2 = up[32 + lane];     // group 1

    for (int l0 = 0; l0 < L_; l0 += 32) {
        float uv = uv_next;
        uv_next = uv_next2;
        if (l0 + 64 < L_) uv_next2 = up[l0 + 64 + lane];
        #pragma unroll
        for (int t = 0; t < 32; t++) {
            float ut = __shfl_sync(0xffffffffu, uv, t);
            float t0  = fmaf(-wi, xi, ut);
            float t1  = wi * xr;
            float nxr = fmaf(wr, xr, t0);
            float nxi = fmaf(wr, xi, t1);
            xr = nxr; xi = nxi;
            red[wid][t][lane] = fmaf(cr, xr, nci * xi);
        }
        __syncwarp();
        const float2* rp = (const float2*)red[wid][lane];
        float s0 = 0.0f, s1 = 0.0f, s2 = 0.0f, s3 = 0.0f;
        #pragma unroll
        for (int j = 0; j < 8; j++) {
            float2 a = rp[2 * j], c2 = rp[2 * j + 1];
            s0 += a.x; s1 += a.y; s2 += c2.x; s3 += c2.y;
        }
        float y = fmaf(Dh, uv, (s0 + s1) + (s2 + s3));   // uv = u at t=lane
        float gv = 0.5f * y * (1.0f + erff(y * 0.70710678118654752f));
        gp[l0 + lane] = __float2half(gv);
        __syncwarp();
    }
}

// ---------------------------------------------------------------------------
// Kernel 3: mma.sync fp16 GEMM + GLU, single pass (W fp16, g fp16, fp32 acc).
// CTA: M=128 (rows 0-63 = a-channels h0.., rows 64-127 = gate channels
// 512+h0..), N=128 l-cols, BK=32, 3-stage cp.async pipeline.
// B from natural g[b][h][l] as [k=h][n=l] tiles via ldmatrix.x4.trans.
// 8 warps (4M x 2N), warp tile 32x64, 2 CTAs/SM.
// ---------------------------------------------------------------------------
#define BK 32
#define SSTR 80                              // A rows: 64B + 16B pad
#define SSTRB 272                            // B rows: 256B + 16B pad
#define TILE_A 10240                         // 128 * 80
#define TILE_B (BK * SSTRB)                  // 8704
#define OFF_B  TILE_A
#define STAGEB (TILE_A + TILE_B)             // 18944
#define NSTAGE (H_ / BK)                     // 16
#define SMEM_BYTES (3 * STAGEB)              // 56832
#define BSRC_STRIDE ((size_t)BK * L_ * 2)    // 262144 bytes per stage

__global__ __launch_bounds__(256, 2) void gemm_glu_mma(const float* __restrict__ bias,
                                                       float* __restrict__ out)
{
    extern __shared__ char smem[];
    const int tid  = threadIdx.x;
    const int wid  = tid >> 5;
    const int lane = tid & 31;

    const int b  = blockIdx.x >> 5;
    const int l0 = (blockIdx.x & 31) * 128;
    const int h0 = blockIdx.y * 64;

    const uint32_t sb = smem_u32(smem);
    const int wm = wid >> 1;
    const int wn = wid & 1;

    // ---- hoisted ldsm byte offsets (relative to stage base) ----
    uint32_t aoff[2], boff[4];
    {
        int rr0 = wm * 32 + (lane & 15);
        int ka  = (lane >> 4) << 4;
        aoff[0] = (uint32_t)((rr0 +  0) * SSTR + ka);
        aoff[1] = (uint32_t)((rr0 + 16) * SSTR + ka);
        int rowb = (lane & 15) * SSTRB;
        int nbase = wn * 64 + ((lane >> 4) << 3);
        #pragma unroll
        for (int jb = 0; jb < 4; jb++)
            boff[jb] = (uint32_t)(OFF_B + rowb + (nbase + jb * 16) * 2);
    }

    // ---- cp.async mapping: 4 x 16B per thread per stage (1024 txns) ----
    // j0,j1: A (Wf): 128 rows x 4 segs = 512 txns; per-stage src stride 64B
    // j2,j3: B (g):  32 rows x 16 segs = 512 txns; per-stage src stride BK*L*2
    const char* srcs[4];
    uint32_t    dsts[4];
    #pragma unroll
    for (int j = 0; j < 2; j++) {
        int id  = tid + 256 * j;
        int row = id >> 2;
        int seg = id & 3;
        int arow = h0 + row + ((row >= 64) ? 448 : 0);
        srcs[j] = (const char*)(d_Wf + (size_t)arow * H_) + seg * 16;
        dsts[j] = sb + row * SSTR + seg * 16;
    }
    #pragma unroll
    for (int j = 2; j < 4; j++) {
        int id  = tid + 256 * (j - 2);
        int row = id >> 4;
        int seg = id & 15;
        const __half* base = d_g + (size_t)b * H_ * L_;
        srcs[j] = (const char*)(base + (size_t)row * L_ + l0) + seg * 16;
        dsts[j] = sb + OFF_B + row * SSTRB + seg * 16;
    }

    // prologue
    #pragma unroll
    for (int j = 0; j < 2; j++) CP_ASYNC16(dsts[j], srcs[j]);
    #pragma unroll
    for (int j = 2; j < 4; j++) CP_ASYNC16(dsts[j], srcs[j]);
    CP_COMMIT();
    #pragma unroll
    for (int j = 0; j < 2; j++) CP_ASYNC16(dsts[j] + STAGEB, srcs[j] + 64);
    #pragma unroll
    for (int j = 2; j < 4; j++) CP_ASYNC16(dsts[j] + STAGEB, srcs[j] + BSRC_STRIDE);
    CP_COMMIT();

    float acc[2][8][4];
    #pragma unroll
    for (int mf = 0; mf < 2; mf++)
        #pragma unroll
        for (int nf = 0; nf < 8; nf++)
            #pragma unroll
            for (int e = 0; e < 4; e++) acc[mf][nf][e] = 0.0f;

    for (int s = 0; s < NSTAGE; s++) {
        if (s == NSTAGE - 1) { CP_WAIT0(); } else { CP_WAIT1(); }
        __syncthreads();

        const uint32_t st = sb + (uint32_t)(s % 3) * STAGEB;

        #pragma unroll
        for (int ks = 0; ks < 2; ks++) {
            const uint32_t ksoA = (uint32_t)(ks * 32);
            const uint32_t ksoB = (uint32_t)(ks * 16 * SSTRB);
            uint32_t aF[2][4], bF[4][4];
            #pragma unroll
            for (int mf = 0; mf < 2; mf++)
                ldsm4(aF[mf], st + aoff[mf] + ksoA);
            #pragma unroll
            for (int jb = 0; jb < 4; jb++)
                ldsm4t(bF[jb], st + boff[jb] + ksoB);
            #pragma unroll
            for (int mf = 0; mf < 2; mf++)
                #pragma unroll
                for (int jb = 0; jb < 4; jb++)
                    #pragma unroll
                    for (int hh = 0; hh < 2; hh++)
                        mma16816(acc[mf][jb * 2 + hh], aF[mf],
                                 bF[jb][2 * hh], bF[jb][2 * hh + 1]);
        }

        if (s + 2 < NSTAGE) {
            uint32_t dbo = (uint32_t)((s + 2) % 3) * STAGEB;
            #pragma unroll
            for (int j = 0; j < 2; j++)
                CP_ASYNC16(dsts[j] + dbo, srcs[j] + (size_t)(s + 2) * 64);
            #pragma unroll
            for (int j = 2; j < 4; j++)
                CP_ASYNC16(dsts[j] + dbo, srcs[j] + (size_t)(s + 2) * BSRC_STRIDE);
            CP_COMMIT();
        }
    }
    __syncthreads();

    // ---- epilogue: GLU ----
    float* sg = (float*)smem;               // [64][130] f32 = 33280 B
    const int r0 = (lane >> 2);
    const int c0 = (lane & 3) * 2;

    if (wm >= 2) {
        #pragma unroll
        for (int mf = 0; mf < 2; mf++) {
            int row = wm * 32 + mf * 16 + r0;     // 64..127
            int grow = row - 64;
            float bg  = bias[H_ + h0 + grow];
            float bg2 = bias[H_ + h0 + grow + 8];
            #pragma unroll
            for (int nf = 0; nf < 8; nf++) {
                int col = wn * 64 + nf * 8 + c0;
                *(float2*)&sg[grow * 130 + col] =
                    make_float2(acc[mf][nf][0] + bg, acc[mf][nf][1] + bg);
                *(float2*)&sg[(grow + 8) * 130 + col] =
                    make_float2(acc[mf][nf][2] + bg2, acc[mf][nf][3] + bg2);
            }
        }
    }
    __syncthreads();
    if (wm < 2) {
        #pragma unroll
        for (int mf = 0; mf < 2; mf++) {
            int row = wm * 32 + mf * 16 + r0;     // 0..63
            int h  = h0 + row;
            float ba  = bias[h];
            float ba2 = bias[h + 8];
            float* ob  = out + ((size_t)b * H_ + h) * L_ + l0;
            float* ob2 = out + ((size_t)b * H_ + h + 8) * L_ + l0;
            #pragma unroll
            for (int nf = 0; nf < 8; nf++) {
                int col = wn * 64 + nf * 8 + c0;
                float2 g0 = *(const float2*)&sg[row * 130 + col];
                float2 g1 = *(const float2*)&sg[(row + 8) * 130 + col];
                float2 o0, o1;
                o0.x = (acc[mf][nf][0] + ba)  / (1.0f + expf(-g0.x));
                o0.y = (acc[mf][nf][1] + ba)  / (1.0f + expf(-g0.y));
                o1.x = (acc[mf][nf][2] + ba2) / (1.0f + expf(-g1.x));
                o1.y = (acc[mf][nf][3] + ba2) / (1.0f + expf(-g1.y));
                *(float2*)(ob  + col) = o0;
                *(float2*)(ob2 + col) = o1;
            }
        }
    }
}

// ---------------------------------------------------------------------------
extern "C" void kernel_launch(void* const* d_in, const int* in_sizes, int n_in,
                              void* d_out, int out_size)
{
    const float* u          = (const float*)d_in[0];
    const float* log_dt     = (const float*)d_in[1];
    const float* log_A_real = (const float*)d_in[2];
    const float* A_imag     = (const float*)d_in[3];
    const float* C          = (const float*)d_in[4];
    const float* D          = (const float*)d_in[5];
    const float* W_out      = (const float*)d_in[6];
    const float* b_out      = (const float*)d_in[7];
    float* out = (float*)d_out;

    static bool attr_set = false;
    if (!attr_set) {
        cudaFuncSetAttribute(gemm_glu_mma, cudaFuncAttributeMaxDynamicSharedMemorySize,
                             SMEM_BYTES);
        attr_set = true;
    }

    prep_kernel<<<(HN + 127) / 128, 128>>>(log_dt, log_A_real, A_imag, C);
    wconv_kernel<<<(O_ * H_ + 255) / 256, 256>>>(W_out);
    scan_kernel<<<(B_ * H_) / 8, 256>>>(u, D);

    dim3 grid(B_ * (L_ / 128), H_ / 64);    // (256, 8)
    gemm_glu_mma<<<grid, 256, SMEM_BYTES>>>(b_out, out);
}